// round 7
// baseline (speedup 1.0000x reference)
#include <cuda_runtime.h>
#include <cuda_fp16.h>
#include <math.h>
#include <stdint.h>

// Problem constants
#define BATCH 128
#define NOBJ  36
#define NNODE (BATCH*NOBJ)   // 4608
#define QD    2400
#define QDP   2432

typedef __half fp16;

#define SWZ128(o) ((o) ^ (((o) >> 3) & 0x70))

__device__ __forceinline__ uint32_t smem_u32(const void* p) {
    uint32_t a;
    asm("{ .reg .u64 t; cvta.to.shared.u64 t, %1; cvt.u32.u64 %0, t; }" : "=r"(a) : "l"(p));
    return a;
}
__device__ __forceinline__ void cpa16(uint32_t s, const void* g) {
    asm volatile("cp.async.cg.shared.global [%0], [%1], 16;" :: "r"(s), "l"(g));
}
#define CP_COMMIT() asm volatile("cp.async.commit_group;" ::: "memory")
#define CP_WAIT1()  asm volatile("cp.async.wait_group 1;" ::: "memory")
#define CP_WAIT0()  asm volatile("cp.async.wait_group 0;" ::: "memory")

__device__ __forceinline__ void ldmx4(uint32_t& r0, uint32_t& r1, uint32_t& r2, uint32_t& r3, uint32_t addr) {
    asm volatile("ldmatrix.sync.aligned.m8n8.x4.shared.b16 {%0,%1,%2,%3}, [%4];"
                 : "=r"(r0), "=r"(r1), "=r"(r2), "=r"(r3) : "r"(addr));
}
// fp32-accum fp16 MMA
__device__ __forceinline__ void mma16816(float* c, const uint32_t* a, uint32_t b0, uint32_t b1) {
    asm volatile(
        "mma.sync.aligned.m16n8k16.row.col.f32.f16.f16.f32 "
        "{%0,%1,%2,%3}, {%4,%5,%6,%7}, {%8,%9}, {%0,%1,%2,%3};"
        : "+f"(c[0]), "+f"(c[1]), "+f"(c[2]), "+f"(c[3])
        : "r"(a[0]), "r"(a[1]), "r"(a[2]), "r"(a[3]), "r"(b0), "r"(b1));
}
// fp16-accum fp16 MMA (for the lo term; magnitude ~2^-11 of total)
__device__ __forceinline__ void mma16816h(uint32_t* c, const uint32_t* a, uint32_t b0, uint32_t b1) {
    asm volatile(
        "mma.sync.aligned.m16n8k16.row.col.f16.f16.f16.f16 "
        "{%0,%1}, {%2,%3,%4,%5}, {%6,%7}, {%0,%1};"
        : "+r"(c[0]), "+r"(c[1])
        : "r"(a[0]), "r"(a[1]), "r"(a[2]), "r"(a[3]), "r"(b0), "r"(b1));
}

// ==================== scratch (no allocations allowed) ====================
__device__ __align__(128) fp16 g_qe16[128 * QDP];
__device__ __align__(128) fp16 g_ob16[NNODE * 2048];
__device__ __align__(128) fp16 g_WqTh[2048 * QDP];
__device__ __align__(128) fp16 g_WqTl[2048 * QDP];
__device__ __align__(128) fp16 g_WvTh[2048 * 2048];
__device__ __align__(128) fp16 g_WvTl[2048 * 2048];
__device__ __align__(128) fp16 g_W1Th[1024 * 2048];
__device__ __align__(128) fp16 g_W1Tl[1024 * 2048];
__device__ __align__(128) fp16 g_W2Th[1024 * 1024];
__device__ __align__(128) fp16 g_W2Tl[1024 * 1024];
__device__ __align__(128) fp16 g_W3Th[2560 * 1024];
__device__ __align__(128) fp16 g_W3Tl[2560 * 1024];
__device__ __align__(128) fp16 g_x16 [NNODE * 2048];
__device__ __align__(128) fp16 g_g116[NNODE * 1024];
__device__ __align__(128) fp16 g_g216[NNODE * 1024];

__device__ float g_q    [128 * 2048];
__device__ float g_qpart[8 * 128 * 2048];
__device__ float g_h    [NNODE * 2560];
__device__ float g_g1   [NNODE * 1024];
__device__ float g_g2   [NNODE * 1024];
__device__ float g_als  [NNODE * 5];
__device__ float g_ald  [NNODE * 5];

// ==================== conversion kernels ====================
__global__ void conv16_k(const float* __restrict__ in, fp16* __restrict__ o16, int R, int C, int Cp)
{
    int idx = blockIdx.x * blockDim.x + threadIdx.x;
    int cq = Cp >> 2;
    if (idx >= R * cq) return;
    int r = idx / cq;
    int c4 = (idx - r * cq) * 4;
    float4 v = make_float4(0.f, 0.f, 0.f, 0.f);
    if (c4 < C) v = *(const float4*)(in + (size_t)r * C + c4);
    *(__half2*)(o16 + (size_t)r * Cp + c4)     = __floats2half2_rn(v.x, v.y);
    *(__half2*)(o16 + (size_t)r * Cp + c4 + 2) = __floats2half2_rn(v.z, v.w);
}

// transpose + fp16 2-split: W fp32 [K,N] -> Th/Tl fp16 [N,Kp]
__global__ __launch_bounds__(256) void tsplit_k(const float* __restrict__ W,
                                                fp16* __restrict__ Th, fp16* __restrict__ Tl,
                                                int K, int N, int Kp)
{
    __shared__ float t[32][33];
    int n0 = blockIdx.x * 32, k0 = blockIdx.y * 32;
    int tx = threadIdx.x & 31, ty = threadIdx.x >> 5;
    #pragma unroll
    for (int i = 0; i < 4; i++) {
        int k = k0 + ty + i * 8;
        t[ty + i * 8][tx] = (k < K) ? W[(size_t)k * N + n0 + tx] : 0.f;
    }
    __syncthreads();
    #pragma unroll
    for (int i = 0; i < 4; i++) {
        int n = n0 + ty + i * 8;
        int k = k0 + tx;
        float v = t[tx][ty + i * 8];
        fp16 h = __float2half_rn(v);
        fp16 l = __float2half_rn(v - __half2float(h));
        Th[(size_t)n * Kp + k] = h;
        Tl[(size_t)n * Kp + k] = l;
    }
}

// combine split-K 8 q partials + bias
__global__ void combq_k(const float* __restrict__ parts, const float* __restrict__ bq, float* __restrict__ q)
{
    int idx = blockIdx.x * blockDim.x + threadIdx.x;
    if (idx >= 128 * 2048) return;
    const size_t S = (size_t)128 * 2048;
    int c = idx & 2047;
    float s = bq[c];
    #pragma unroll
    for (int p = 0; p < 8; p++) s += parts[idx + p * S];
    q[idx] = s;
}

// ==================== fp16 2-term GEMM ====================
// C[M,N] = A[M,Kp] @ (Bh+Bl)[N,Kp]^T ; CTA tile 128x128, KC=64, 512 threads
// hi term: fp32 accum; lo term: fp16 accum (tiny magnitude)
// 16 warps in 4x4 grid, warp tile 32x32
// mode 0: Cf[splitStride*z + row*N+col] = acc
// mode 2: C16[row*N+col] = fp16((acc + bias[col]) * qmul[(row/36)*N+col])
#define KC 64
#define BUFSZ 49152u          // A 16K + Bh 16K + Bl 16K
#define GEMM_SMEM (2*BUFSZ + 1024)

__global__ __launch_bounds__(512, 1) void gemm2(
    const fp16* __restrict__ A,
    const fp16* __restrict__ Bh, const fp16* __restrict__ Bl,
    int N, int Kp, int kcTotal, int kcPerSplit,
    const float* __restrict__ bias, const float* __restrict__ qmul,
    float* __restrict__ Cf, fp16* __restrict__ C16,
    int mode, size_t splitStride)
{
    extern __shared__ char dsm[];
    uint32_t sb = smem_u32(dsm);
    sb = (sb + 1023u) & ~1023u;

    const int tid = threadIdx.x;
    const int wid = tid >> 5;
    const int L   = tid & 31;
    const int m0 = blockIdx.y * 128;
    const int n0 = blockIdx.x * 128;
    const int kc0 = blockIdx.z * kcPerSplit;
    int kc1 = kc0 + kcPerSplit; if (kc1 > kcTotal) kc1 = kcTotal;
    const int ncl = kc1 - kc0;

    const int wm = (wid & 3) * 32;     // 4 warp-rows
    const int wn = (wid >> 2) * 32;    // 4 warp-cols

    float    acc [2][4][4];            // hi term, fp32
    uint32_t accL[2][4][2];            // lo term, packed fp16x2
    #pragma unroll
    for (int i = 0; i < 2; i++)
        #pragma unroll
        for (int j = 0; j < 4; j++) {
            #pragma unroll
            for (int k = 0; k < 4; k++) acc[i][j][k] = 0.f;
            accL[i][j][0] = 0u; accL[i][j][1] = 0u;
        }

    // ldmatrix per-lane addressing (SW128 over 128B rows)
    const int rA = ((L >> 3) & 1) * 8 + (L & 7);
    const int cA = (L >> 4) * 16;
    const int rB = (L >> 4) * 8 + (L & 7);
    const int cB = ((L >> 3) & 1) * 16;

    uint32_t offA[2], mskA[2];
    #pragma unroll
    for (int mf = 0; mf < 2; mf++) {
        int row = wm + mf * 16 + rA;
        offA[mf] = (uint32_t)(row * 128);
        mskA[mf] = (uint32_t)((row & 7) * 16);
    }
    uint32_t offB[2], mskB[2];
    #pragma unroll
    for (int nf2 = 0; nf2 < 2; nf2++) {
        int row = wn + nf2 * 16 + rB;
        offB[nf2] = (uint32_t)(row * 128);
        mskB[nf2] = (uint32_t)((row & 7) * 16);
    }

    // layout per buffer: A @0 (16KB), Bh @16K, Bl @32K
    auto load_chunk = [&](int c, int s) {
        const int k0 = c * KC;
        uint32_t base = sb + (uint32_t)s * BUFSZ;
        #pragma unroll
        for (int i = 0; i < 2; i++) {
            int u = tid + i * 512;
            int r = u >> 3, uc = u & 7;
            uint32_t so = SWZ128((uint32_t)(r * 128 + uc * 16));
            size_t goA = (size_t)(m0 + r) * Kp + k0 + uc * 8;
            size_t goB = (size_t)(n0 + r) * Kp + k0 + uc * 8;
            cpa16(base + so,           A  + goA);
            cpa16(base + 16384u + so,  Bh + goB);
            cpa16(base + 32768u + so,  Bl + goB);
        }
    };

    load_chunk(kc0, 0); CP_COMMIT();

    for (int cc = 0; cc < ncl; cc++) {
        if (cc + 1 < ncl) {
            load_chunk(kc0 + cc + 1, (cc + 1) & 1);
            CP_COMMIT();
            CP_WAIT1();
        } else {
            CP_WAIT0();
        }
        __syncthreads();

        uint32_t base = sb + (uint32_t)(cc & 1) * BUFSZ;
        #pragma unroll
        for (int ks = 0; ks < 4; ks++) {
            const uint32_t kb = (uint32_t)(ks * 32);
            uint32_t af[2][4];
            #pragma unroll
            for (int mf = 0; mf < 2; mf++) {
                uint32_t rel = offA[mf] + ((kb + cA) ^ mskA[mf]);
                ldmx4(af[mf][0], af[mf][1], af[mf][2], af[mf][3], base + rel);
            }
            #pragma unroll
            for (int nf2 = 0; nf2 < 2; nf2++) {
                uint32_t rel = offB[nf2] + ((kb + cB) ^ mskB[nf2]);
                uint32_t bh[4], bl[4];
                ldmx4(bh[0], bh[1], bh[2], bh[3], base + 16384u + rel);
                ldmx4(bl[0], bl[1], bl[2], bl[3], base + 32768u + rel);
                #pragma unroll
                for (int mf = 0; mf < 2; mf++) {
                    mma16816 (acc [mf][nf2*2],   af[mf], bh[0], bh[1]);
                    mma16816 (acc [mf][nf2*2+1], af[mf], bh[2], bh[3]);
                    mma16816h(accL[mf][nf2*2],   af[mf], bl[0], bl[1]);
                    mma16816h(accL[mf][nf2*2+1], af[mf], bl[2], bl[3]);
                }
            }
        }
        __syncthreads();
    }

    // epilogue
    const int rEp = (L >> 2);
    const int cEp = (L & 3) * 2;
    #pragma unroll
    for (int mf = 0; mf < 2; mf++) {
        #pragma unroll
        for (int half = 0; half < 2; half++) {
            int row = m0 + wm + mf * 16 + rEp + half * 8;
            if (mode == 0) {
                float* dst = Cf + splitStride * blockIdx.z + (size_t)row * N;
                #pragma unroll
                for (int nf = 0; nf < 4; nf++) {
                    __half2 lo = *(__half2*)&accL[mf][nf][half];
                    int col = n0 + wn + nf * 8 + cEp;
                    float2 v;
                    v.x = acc[mf][nf][half*2 + 0] + __half2float(lo.x);
                    v.y = acc[mf][nf][half*2 + 1] + __half2float(lo.y);
                    *(float2*)(dst + col) = v;
                }
            } else {  // mode 2: hadamard, write fp16
                const float* qrow = qmul + (size_t)(row / NOBJ) * N;
                fp16* d16 = C16 + (size_t)row * N;
                #pragma unroll
                for (int nf = 0; nf < 4; nf++) {
                    __half2 lo = *(__half2*)&accL[mf][nf][half];
                    int col = n0 + wn + nf * 8 + cEp;
                    float o0 = (acc[mf][nf][half*2+0] + __half2float(lo.x) + bias[col])   * qrow[col];
                    float o1 = (acc[mf][nf][half*2+1] + __half2float(lo.y) + bias[col+1]) * qrow[col+1];
                    *(__half2*)(d16 + col) = __floats2half2_rn(o0, o1);
                }
            }
        }
    }
}

// ==================== attention logits ====================
__global__ void al_k(const float* __restrict__ h,
                     const float* __restrict__ a_s, const float* __restrict__ a_d,
                     float* __restrict__ als, float* __restrict__ ald,
                     int total, int H, int C)
{
    int w = (blockIdx.x * blockDim.x + threadIdx.x) >> 5;
    int lane = threadIdx.x & 31;
    if (w >= total) return;
    int n = w / H, hd = w - n * H;
    const float* hp = h + (size_t)n * H * C + (size_t)hd * C;
    const float* sp = a_s + (size_t)hd * C;
    const float* dp = a_d + (size_t)hd * C;
    float s = 0.f, d = 0.f;
    for (int c = lane; c < C; c += 32) {
        float hv = hp[c];
        s = fmaf(hv, sp[c], s);
        d = fmaf(hv, dp[c], d);
    }
    #pragma unroll
    for (int o = 16; o > 0; o >>= 1) {
        s += __shfl_down_sync(0xffffffffu, s, o);
        d += __shfl_down_sync(0xffffffffu, d, o);
    }
    if (lane == 0) { als[w] = s; ald[w] = d; }
}

__device__ __forceinline__ void softmax36(const float* ss, const float* sd,
                                          float (*aT)[40], int i)
{
    float di = sd[i];
    float ev[36];
    float m = -3.4e38f;
    #pragma unroll
    for (int j = 0; j < 36; j++) {
        float e = ss[j] + di;
        e = (e > 0.f) ? e : 0.2f * e;
        ev[j] = e;
        m = fmaxf(m, e);
    }
    float sum = 0.f;
    #pragma unroll
    for (int j = 0; j < 36; j++) { float x = expf(ev[j] - m); ev[j] = x; sum += x; }
    float inv = 1.0f / (sum + 1e-16f);
    #pragma unroll
    for (int j = 0; j < 36; j++) aT[j][i] = ev[j] * inv;
}

// GAT aggregation C=256 concat + relu (+residual), write fp32 + fp16
__global__ __launch_bounds__(256) void gat_agg256(
    const float* __restrict__ h, const float* __restrict__ als, const float* __restrict__ ald,
    const float* __restrict__ bias, const float* __restrict__ resid,
    float* __restrict__ out, fp16* __restrict__ out16, int H)
{
    __shared__ float sh[36][256];
    __shared__ float aT[36][40];
    __shared__ float ss[36], sd[36];

    const int bh = blockIdx.x;
    const int b = bh / H, hd = bh - b * H;
    const int tid = threadIdx.x;
    const int stride = H * 256;
    const float* hbase = h + (size_t)(b * NOBJ) * stride + hd * 256;

    for (int idx = tid; idx < 36 * 256; idx += 256) {
        int i = idx >> 8, c = idx & 255;
        sh[i][c] = hbase[(size_t)i * stride + c];
    }
    if (tid < 36) {
        ss[tid] = als[(size_t)(b * NOBJ + tid) * H + hd];
        sd[tid] = ald[(size_t)(b * NOBJ + tid) * H + hd];
    }
    __syncthreads();
    if (tid < 36) softmax36(ss, sd, aT, tid);
    __syncthreads();

    const int c = tid;
    float acc[36];
    #pragma unroll
    for (int i = 0; i < 36; i++) acc[i] = 0.f;

    #pragma unroll 4
    for (int j = 0; j < 36; j++) {
        float hv = sh[j][c];
        #pragma unroll
        for (int it = 0; it < 9; it++) {
            float4 a = *(const float4*)&aT[j][it * 4];
            acc[it*4+0] = fmaf(a.x, hv, acc[it*4+0]);
            acc[it*4+1] = fmaf(a.y, hv, acc[it*4+1]);
            acc[it*4+2] = fmaf(a.z, hv, acc[it*4+2]);
            acc[it*4+3] = fmaf(a.w, hv, acc[it*4+3]);
        }
    }

    float bv = bias[hd * 256 + c];
    #pragma unroll 4
    for (int i = 0; i < 36; i++) {
        size_t oi = (size_t)(b * NOBJ + i) * stride + hd * 256 + c;
        float o = fmaxf(acc[i] + bv, 0.f);
        if (resid) o += resid[oi];
        out[oi] = o;
        out16[oi] = __float2half_rn(o);
    }
}

// GAT layer 3: C=512, H=5, mean over heads + b3
__global__ __launch_bounds__(256) void gat_mean_k(
    const float* __restrict__ h, const float* __restrict__ als, const float* __restrict__ ald,
    const float* __restrict__ bias, float* __restrict__ out)
{
    __shared__ float sh[36][256];
    __shared__ float aT[36][40];
    __shared__ float ss[36], sd[36];

    const int b = blockIdx.x;
    const int coff = blockIdx.y * 256;
    const int tid = threadIdx.x;

    float acc[36];
    #pragma unroll
    for (int i = 0; i < 36; i++) acc[i] = 0.f;

    for (int hd = 0; hd < 5; hd++) {
        __syncthreads();
        for (int idx = tid; idx < 36 * 256; idx += 256) {
            int i = idx >> 8, c = idx & 255;
            sh[i][c] = h[(size_t)(b * NOBJ + i) * 2560 + hd * 512 + coff + c];
        }
        if (tid < 36) {
            ss[tid] = als[(size_t)(b * NOBJ + tid) * 5 + hd];
            sd[tid] = ald[(size_t)(b * NOBJ + tid) * 5 + hd];
        }
        __syncthreads();
        if (tid < 36) softmax36(ss, sd, aT, tid);
        __syncthreads();

        const int c = tid;
        #pragma unroll 4
        for (int j = 0; j < 36; j++) {
            float hv = sh[j][c];
            #pragma unroll
            for (int it = 0; it < 9; it++) {
                float4 a = *(const float4*)&aT[j][it * 4];
                acc[it*4+0] = fmaf(a.x, hv, acc[it*4+0]);
                acc[it*4+1] = fmaf(a.y, hv, acc[it*4+1]);
                acc[it*4+2] = fmaf(a.z, hv, acc[it*4+2]);
                acc[it*4+3] = fmaf(a.w, hv, acc[it*4+3]);
            }
        }
    }

    float bv = bias[coff + tid];
    #pragma unroll 4
    for (int i = 0; i < 36; i++)
        out[(size_t)(b * NOBJ + i) * 512 + coff + tid] = acc[i] * 0.2f + bv;
}

// ==================== launch ====================
extern "C" void kernel_launch(void* const* d_in, const int* in_sizes, int n_in,
                              void* d_out, int out_size)
{
    const float* qe  = (const float*)d_in[0];
    const float* obj = (const float*)d_in[1];
    const float* Wq  = (const float*)d_in[3];
    const float* bq  = (const float*)d_in[4];
    const float* Wv  = (const float*)d_in[5];
    const float* bv  = (const float*)d_in[6];
    const float* W1  = (const float*)d_in[7];
    const float* a1s = (const float*)d_in[8];
    const float* a1d = (const float*)d_in[9];
    const float* b1  = (const float*)d_in[10];
    const float* W2  = (const float*)d_in[11];
    const float* a2s = (const float*)d_in[12];
    const float* a2d = (const float*)d_in[13];
    const float* b2  = (const float*)d_in[14];
    const float* W3  = (const float*)d_in[15];
    const float* a3s = (const float*)d_in[16];
    const float* a3d = (const float*)d_in[17];
    const float* b3  = (const float*)d_in[18];
    float* out = (float*)d_out;

    fp16 *qe16,*ob16,*WqTh,*WqTl,*WvTh,*WvTl,*W1Th,*W1Tl,*W2Th,*W2Tl,*W3Th,*W3Tl;
    fp16 *x16,*g116,*g216;
    float *q,*qpart,*h,*g1,*g2,*als,*ald;
    cudaGetSymbolAddress((void**)&qe16, g_qe16); cudaGetSymbolAddress((void**)&ob16, g_ob16);
    cudaGetSymbolAddress((void**)&WqTh, g_WqTh); cudaGetSymbolAddress((void**)&WqTl, g_WqTl);
    cudaGetSymbolAddress((void**)&WvTh, g_WvTh); cudaGetSymbolAddress((void**)&WvTl, g_WvTl);
    cudaGetSymbolAddress((void**)&W1Th, g_W1Th); cudaGetSymbolAddress((void**)&W1Tl, g_W1Tl);
    cudaGetSymbolAddress((void**)&W2Th, g_W2Th); cudaGetSymbolAddress((void**)&W2Tl, g_W2Tl);
    cudaGetSymbolAddress((void**)&W3Th, g_W3Th); cudaGetSymbolAddress((void**)&W3Tl, g_W3Tl);
    cudaGetSymbolAddress((void**)&x16,  g_x16);
    cudaGetSymbolAddress((void**)&g116, g_g116); cudaGetSymbolAddress((void**)&g216, g_g216);
    cudaGetSymbolAddress((void**)&q,    g_q);    cudaGetSymbolAddress((void**)&qpart,g_qpart);
    cudaGetSymbolAddress((void**)&h,    g_h);
    cudaGetSymbolAddress((void**)&g1,   g_g1);   cudaGetSymbolAddress((void**)&g2,   g_g2);
    cudaGetSymbolAddress((void**)&als,  g_als);  cudaGetSymbolAddress((void**)&ald,  g_ald);

    cudaFuncSetAttribute(gemm2, cudaFuncAttributeMaxDynamicSharedMemorySize, GEMM_SMEM);

    // conversions / weight prep
    conv16_k<<<(128 * (QDP/4) + 255) / 256, 256>>>(qe, qe16, 128, QD, QDP);
    conv16_k<<<(NNODE * (2048/4) + 255) / 256, 256>>>(obj, ob16, NNODE, 2048, 2048);
    tsplit_k<<<dim3(2048/32, QDP/32), 256>>>(Wq, WqTh, WqTl, QD, 2048, QDP);
    tsplit_k<<<dim3(2048/32, 2048/32), 256>>>(Wv, WvTh, WvTl, 2048, 2048, 2048);
    tsplit_k<<<dim3(1024/32, 2048/32), 256>>>(W1, W1Th, W1Tl, 2048, 1024, 2048);
    tsplit_k<<<dim3(1024/32, 1024/32), 256>>>(W2, W2Th, W2Tl, 1024, 1024, 1024);
    tsplit_k<<<dim3(2560/32, 1024/32), 256>>>(W3, W3Th, W3Tl, 1024, 2560, 1024);

    // q = qe @ Wq (split-K 8) + bq       grid 16 x 1 x 8 = 128 CTAs
    gemm2<<<dim3(16, 1, 8), 512, GEMM_SMEM>>>(qe16, WqTh, WqTl, 2048, QDP, 38, 5,
                                              nullptr, nullptr, qpart, nullptr, 0,
                                              (size_t)128 * 2048);
    combq_k<<<(128 * 2048 + 255) / 256, 256>>>(qpart, bq, q);

    // x = (obj @ Wv + bv) * q  -> fp16   grid 16 x 36
    gemm2<<<dim3(16, 36, 1), 512, GEMM_SMEM>>>(ob16, WvTh, WvTl, 2048, 2048, 32, 32,
                                               bv, q, nullptr, x16, 2, 0);

    // layer 1                            grid 8 x 36
    gemm2<<<dim3(8, 36, 1), 512, GEMM_SMEM>>>(x16, W1Th, W1Tl, 1024, 2048, 32, 32,
                                              nullptr, nullptr, h, nullptr, 0, 0);
    al_k<<<(NNODE * 4 * 32 + 255) / 256, 256>>>(h, a1s, a1d, als, ald, NNODE * 4, 4, 256);
    gat_agg256<<<BATCH * 4, 256>>>(h, als, ald, b1, nullptr, g1, g116, 4);

    // layer 2 (+residual)                grid 8 x 36
    gemm2<<<dim3(8, 36, 1), 512, GEMM_SMEM>>>(g116, W2Th, W2Tl, 1024, 1024, 16, 16,
                                              nullptr, nullptr, h, nullptr, 0, 0);
    al_k<<<(NNODE * 4 * 32 + 255) / 256, 256>>>(h, a2s, a2d, als, ald, NNODE * 4, 4, 256);
    gat_agg256<<<BATCH * 4, 256>>>(h, als, ald, b2, g1, g2, g216, 4);

    // layer 3 (mean over 5 heads)        grid 20 x 36
    gemm2<<<dim3(20, 36, 1), 512, GEMM_SMEM>>>(g216, W3Th, W3Tl, 2560, 1024, 16, 16,
                                               nullptr, nullptr, h, nullptr, 0, 0);
    al_k<<<(NNODE * 5 * 32 + 255) / 256, 256>>>(h, a3s, a3d, als, ald, NNODE * 5, 5, 512);
    gat_mean_k<<<dim3(BATCH, 2), 256>>>(h, als, ald, b3, out);

    (void)in_sizes; (void)n_in; (void)out_size;
}

// round 8
// speedup vs baseline: 1.4495x; 1.4495x over previous
#include <cuda_runtime.h>
#include <cuda_fp16.h>
#include <math.h>
#include <stdint.h>

// Problem constants
#define BATCH 128
#define NOBJ  36
#define NNODE (BATCH*NOBJ)   // 4608
#define QD    2400
#define QDP   2432

typedef __half fp16;

#define SWZ128(o) ((o) ^ (((o) >> 3) & 0x70))

__device__ __forceinline__ uint32_t smem_u32(const void* p) {
    uint32_t a;
    asm("{ .reg .u64 t; cvta.to.shared.u64 t, %1; cvt.u32.u64 %0, t; }" : "=r"(a) : "l"(p));
    return a;
}
__device__ __forceinline__ void cpa16(uint32_t s, const void* g) {
    asm volatile("cp.async.cg.shared.global [%0], [%1], 16;" :: "r"(s), "l"(g));
}
#define CP_COMMIT() asm volatile("cp.async.commit_group;" ::: "memory")
#define CP_WAIT1()  asm volatile("cp.async.wait_group 1;" ::: "memory")
#define CP_WAIT0()  asm volatile("cp.async.wait_group 0;" ::: "memory")

__device__ __forceinline__ void ldmx4(uint32_t& r0, uint32_t& r1, uint32_t& r2, uint32_t& r3, uint32_t addr) {
    asm volatile("ldmatrix.sync.aligned.m8n8.x4.shared.b16 {%0,%1,%2,%3}, [%4];"
                 : "=r"(r0), "=r"(r1), "=r"(r2), "=r"(r3) : "r"(addr));
}
__device__ __forceinline__ void mma16816(float* c, const uint32_t* a, uint32_t b0, uint32_t b1) {
    asm volatile(
        "mma.sync.aligned.m16n8k16.row.col.f32.f16.f16.f32 "
        "{%0,%1,%2,%3}, {%4,%5,%6,%7}, {%8,%9}, {%0,%1,%2,%3};"
        : "+f"(c[0]), "+f"(c[1]), "+f"(c[2]), "+f"(c[3])
        : "r"(a[0]), "r"(a[1]), "r"(a[2]), "r"(a[3]), "r"(b0), "r"(b1));
}

// ==================== scratch (no allocations allowed) ====================
__device__ __align__(128) fp16 g_qe16[128 * QDP];
__device__ __align__(128) fp16 g_ob16[NNODE * 2048];
__device__ __align__(128) fp16 g_WqT [2048 * QDP];
__device__ __align__(128) fp16 g_WvT [2048 * 2048];
__device__ __align__(128) fp16 g_W1T [1024 * 2048];
__device__ __align__(128) fp16 g_W2T [1024 * 1024];
__device__ __align__(128) fp16 g_W3T [2560 * 1024];
__device__ __align__(128) fp16 g_x16 [NNODE * 2048];
__device__ __align__(128) fp16 g_g116[NNODE * 1024];
__device__ __align__(128) fp16 g_g216[NNODE * 1024];

__device__ float g_q    [128 * 2048];
__device__ float g_qpart[8 * 128 * 2048];
__device__ float g_h    [NNODE * 2560];
__device__ float g_g1   [NNODE * 1024];
__device__ float g_g2   [NNODE * 1024];
__device__ float g_als  [NNODE * 5];
__device__ float g_ald  [NNODE * 5];

// ==================== conversion kernels ====================
__global__ void conv16_k(const float* __restrict__ in, fp16* __restrict__ o16, int R, int C, int Cp)
{
    int idx = blockIdx.x * blockDim.x + threadIdx.x;
    int cq = Cp >> 2;
    if (idx >= R * cq) return;
    int r = idx / cq;
    int c4 = (idx - r * cq) * 4;
    float4 v = make_float4(0.f, 0.f, 0.f, 0.f);
    if (c4 < C) v = *(const float4*)(in + (size_t)r * C + c4);
    *(__half2*)(o16 + (size_t)r * Cp + c4)     = __floats2half2_rn(v.x, v.y);
    *(__half2*)(o16 + (size_t)r * Cp + c4 + 2) = __floats2half2_rn(v.z, v.w);
}

// transpose + fp16 convert: W fp32 [K,N] -> WT fp16 [N,Kp]
__global__ __launch_bounds__(256) void tconv_k(const float* __restrict__ W,
                                               fp16* __restrict__ WT,
                                               int K, int N, int Kp)
{
    __shared__ float t[32][33];
    int n0 = blockIdx.x * 32, k0 = blockIdx.y * 32;
    int tx = threadIdx.x & 31, ty = threadIdx.x >> 5;
    #pragma unroll
    for (int i = 0; i < 4; i++) {
        int k = k0 + ty + i * 8;
        t[ty + i * 8][tx] = (k < K) ? W[(size_t)k * N + n0 + tx] : 0.f;
    }
    __syncthreads();
    #pragma unroll
    for (int i = 0; i < 4; i++) {
        int n = n0 + ty + i * 8;
        WT[(size_t)n * Kp + k0 + tx] = __float2half_rn(t[tx][ty + i * 8]);
    }
}

// combine split-K 8 q partials + bias
__global__ void combq_k(const float* __restrict__ parts, const float* __restrict__ bq, float* __restrict__ q)
{
    int idx = blockIdx.x * blockDim.x + threadIdx.x;
    if (idx >= 128 * 2048) return;
    const size_t S = (size_t)128 * 2048;
    int c = idx & 2047;
    float s = bq[c];
    #pragma unroll
    for (int p = 0; p < 8; p++) s += parts[idx + p * S];
    q[idx] = s;
}

// ==================== fp16 single-term GEMM ====================
// C[M,N] = A[M,Kp] @ B[N,Kp]^T ; CTA tile 128x256, KC=64, 512 threads
// 16 warps in 4x4 grid, warp tile 32x64
// mode 0: Cf[splitStride*z + row*N+col] = acc
// mode 2: C16[row*N+col] = fp16((acc + bias[col]) * qmul[(row/36)*N+col])
#define KC 64
#define BUFSZ 49152u          // A 16K + B 32K
#define GEMM_SMEM (2*BUFSZ + 1024)

__global__ __launch_bounds__(512, 1) void gemm1(
    const fp16* __restrict__ A, const fp16* __restrict__ B,
    int N, int Kp, int kcTotal, int kcPerSplit,
    const float* __restrict__ bias, const float* __restrict__ qmul,
    float* __restrict__ Cf, fp16* __restrict__ C16,
    int mode, size_t splitStride)
{
    extern __shared__ char dsm[];
    uint32_t sb = smem_u32(dsm);
    sb = (sb + 1023u) & ~1023u;

    const int tid = threadIdx.x;
    const int wid = tid >> 5;
    const int L   = tid & 31;
    const int m0 = blockIdx.y * 128;
    const int n0 = blockIdx.x * 256;
    const int kc0 = blockIdx.z * kcPerSplit;
    int kc1 = kc0 + kcPerSplit; if (kc1 > kcTotal) kc1 = kcTotal;
    const int ncl = kc1 - kc0;

    const int wm = (wid & 3) * 32;     // 4 warp-rows
    const int wn = (wid >> 2) * 64;    // 4 warp-cols

    float acc[2][8][4];
    #pragma unroll
    for (int i = 0; i < 2; i++)
        #pragma unroll
        for (int j = 0; j < 8; j++)
            #pragma unroll
            for (int k = 0; k < 4; k++) acc[i][j][k] = 0.f;

    // ldmatrix per-lane addressing (SW128 over 128B rows)
    const int rA = ((L >> 3) & 1) * 8 + (L & 7);
    const int cA = (L >> 4) * 16;
    const int rB = (L >> 4) * 8 + (L & 7);
    const int cB = ((L >> 3) & 1) * 16;

    uint32_t offA[2], mskA[2];
    #pragma unroll
    for (int mf = 0; mf < 2; mf++) {
        int row = wm + mf * 16 + rA;
        offA[mf] = (uint32_t)(row * 128);
        mskA[mf] = (uint32_t)((row & 7) * 16);
    }
    uint32_t offB[4], mskB[4];
    #pragma unroll
    for (int nf2 = 0; nf2 < 4; nf2++) {
        int row = wn + nf2 * 16 + rB;
        offB[nf2] = (uint32_t)(row * 128);
        mskB[nf2] = (uint32_t)((row & 7) * 16);
    }

    // layout per buffer: A @0 (16KB), B @16K (32KB)
    auto load_chunk = [&](int c, int s) {
        const int k0 = c * KC;
        uint32_t base = sb + (uint32_t)s * BUFSZ;
        #pragma unroll
        for (int i = 0; i < 2; i++) {            // A: 1024 16B units
            int u = tid + i * 512;
            int r = u >> 3, uc = u & 7;
            uint32_t so = SWZ128((uint32_t)(r * 128 + uc * 16));
            cpa16(base + so, A + (size_t)(m0 + r) * Kp + k0 + uc * 8);
        }
        #pragma unroll
        for (int i = 0; i < 4; i++) {            // B: 2048 16B units
            int u = tid + i * 512;
            int r = u >> 3, uc = u & 7;
            uint32_t so = SWZ128((uint32_t)(r * 128 + uc * 16));
            cpa16(base + 16384u + so, B + (size_t)(n0 + r) * Kp + k0 + uc * 8);
        }
    };

    load_chunk(kc0, 0); CP_COMMIT();

    for (int cc = 0; cc < ncl; cc++) {
        if (cc + 1 < ncl) {
            load_chunk(kc0 + cc + 1, (cc + 1) & 1);
            CP_COMMIT();
            CP_WAIT1();
        } else {
            CP_WAIT0();
        }
        __syncthreads();

        uint32_t base = sb + (uint32_t)(cc & 1) * BUFSZ;
        #pragma unroll
        for (int ks = 0; ks < 4; ks++) {
            const uint32_t kb = (uint32_t)(ks * 32);
            uint32_t af[2][4];
            #pragma unroll
            for (int mf = 0; mf < 2; mf++) {
                uint32_t rel = offA[mf] + ((kb + cA) ^ mskA[mf]);
                ldmx4(af[mf][0], af[mf][1], af[mf][2], af[mf][3], base + rel);
            }
            #pragma unroll
            for (int nf2 = 0; nf2 < 4; nf2++) {
                uint32_t rel = offB[nf2] + ((kb + cB) ^ mskB[nf2]);
                uint32_t bf[4];
                ldmx4(bf[0], bf[1], bf[2], bf[3], base + 16384u + rel);
                #pragma unroll
                for (int mf = 0; mf < 2; mf++) {
                    mma16816(acc[mf][nf2*2],   af[mf], bf[0], bf[1]);
                    mma16816(acc[mf][nf2*2+1], af[mf], bf[2], bf[3]);
                }
            }
        }
        __syncthreads();
    }

    // epilogue
    const int rEp = (L >> 2);
    const int cEp = (L & 3) * 2;
    #pragma unroll
    for (int mf = 0; mf < 2; mf++) {
        #pragma unroll
        for (int half = 0; half < 2; half++) {
            int row = m0 + wm + mf * 16 + rEp + half * 8;
            if (mode == 0) {
                float* dst = Cf + splitStride * blockIdx.z + (size_t)row * N;
                #pragma unroll
                for (int nf = 0; nf < 8; nf++) {
                    int col = n0 + wn + nf * 8 + cEp;
                    float2 v;
                    v.x = acc[mf][nf][half*2 + 0];
                    v.y = acc[mf][nf][half*2 + 1];
                    *(float2*)(dst + col) = v;
                }
            } else {  // mode 2: hadamard, write fp16
                const float* qrow = qmul + (size_t)(row / NOBJ) * N;
                fp16* d16 = C16 + (size_t)row * N;
                #pragma unroll
                for (int nf = 0; nf < 8; nf++) {
                    int col = n0 + wn + nf * 8 + cEp;
                    float o0 = (acc[mf][nf][half*2+0] + bias[col])   * qrow[col];
                    float o1 = (acc[mf][nf][half*2+1] + bias[col+1]) * qrow[col+1];
                    *(__half2*)(d16 + col) = __floats2half2_rn(o0, o1);
                }
            }
        }
    }
}

// ==================== attention logits ====================
__global__ void al_k(const float* __restrict__ h,
                     const float* __restrict__ a_s, const float* __restrict__ a_d,
                     float* __restrict__ als, float* __restrict__ ald,
                     int total, int H, int C)
{
    int w = (blockIdx.x * blockDim.x + threadIdx.x) >> 5;
    int lane = threadIdx.x & 31;
    if (w >= total) return;
    int n = w / H, hd = w - n * H;
    const float* hp = h + (size_t)n * H * C + (size_t)hd * C;
    const float* sp = a_s + (size_t)hd * C;
    const float* dp = a_d + (size_t)hd * C;
    float s = 0.f, d = 0.f;
    for (int c = lane; c < C; c += 32) {
        float hv = hp[c];
        s = fmaf(hv, sp[c], s);
        d = fmaf(hv, dp[c], d);
    }
    #pragma unroll
    for (int o = 16; o > 0; o >>= 1) {
        s += __shfl_down_sync(0xffffffffu, s, o);
        d += __shfl_down_sync(0xffffffffu, d, o);
    }
    if (lane == 0) { als[w] = s; ald[w] = d; }
}

__device__ __forceinline__ void softmax36(const float* ss, const float* sd,
                                          float (*aT)[40], int i)
{
    float di = sd[i];
    float ev[36];
    float m = -3.4e38f;
    #pragma unroll
    for (int j = 0; j < 36; j++) {
        float e = ss[j] + di;
        e = (e > 0.f) ? e : 0.2f * e;
        ev[j] = e;
        m = fmaxf(m, e);
    }
    float sum = 0.f;
    #pragma unroll
    for (int j = 0; j < 36; j++) { float x = expf(ev[j] - m); ev[j] = x; sum += x; }
    float inv = 1.0f / (sum + 1e-16f);
    #pragma unroll
    for (int j = 0; j < 36; j++) aT[j][i] = ev[j] * inv;
}

// GAT aggregation C=256 concat + relu (+residual), write fp32 + fp16
__global__ __launch_bounds__(256) void gat_agg256(
    const float* __restrict__ h, const float* __restrict__ als, const float* __restrict__ ald,
    const float* __restrict__ bias, const float* __restrict__ resid,
    float* __restrict__ out, fp16* __restrict__ out16, int H)
{
    __shared__ float sh[36][256];
    __shared__ float aT[36][40];
    __shared__ float ss[36], sd[36];

    const int bh = blockIdx.x;
    const int b = bh / H, hd = bh - b * H;
    const int tid = threadIdx.x;
    const int stride = H * 256;
    const float* hbase = h + (size_t)(b * NOBJ) * stride + hd * 256;

    for (int idx = tid; idx < 36 * 256; idx += 256) {
        int i = idx >> 8, c = idx & 255;
        sh[i][c] = hbase[(size_t)i * stride + c];
    }
    if (tid < 36) {
        ss[tid] = als[(size_t)(b * NOBJ + tid) * H + hd];
        sd[tid] = ald[(size_t)(b * NOBJ + tid) * H + hd];
    }
    __syncthreads();
    if (tid < 36) softmax36(ss, sd, aT, tid);
    __syncthreads();

    const int c = tid;
    float acc[36];
    #pragma unroll
    for (int i = 0; i < 36; i++) acc[i] = 0.f;

    #pragma unroll 4
    for (int j = 0; j < 36; j++) {
        float hv = sh[j][c];
        #pragma unroll
        for (int it = 0; it < 9; it++) {
            float4 a = *(const float4*)&aT[j][it * 4];
            acc[it*4+0] = fmaf(a.x, hv, acc[it*4+0]);
            acc[it*4+1] = fmaf(a.y, hv, acc[it*4+1]);
            acc[it*4+2] = fmaf(a.z, hv, acc[it*4+2]);
            acc[it*4+3] = fmaf(a.w, hv, acc[it*4+3]);
        }
    }

    float bv = bias[hd * 256 + c];
    #pragma unroll 4
    for (int i = 0; i < 36; i++) {
        size_t oi = (size_t)(b * NOBJ + i) * stride + hd * 256 + c;
        float o = fmaxf(acc[i] + bv, 0.f);
        if (resid) o += resid[oi];
        out[oi] = o;
        out16[oi] = __float2half_rn(o);
    }
}

// GAT layer 3: C=512, H=5, mean over heads + b3
__global__ __launch_bounds__(256) void gat_mean_k(
    const float* __restrict__ h, const float* __restrict__ als, const float* __restrict__ ald,
    const float* __restrict__ bias, float* __restrict__ out)
{
    __shared__ float sh[36][256];
    __shared__ float aT[36][40];
    __shared__ float ss[36], sd[36];

    const int b = blockIdx.x;
    const int coff = blockIdx.y * 256;
    const int tid = threadIdx.x;

    float acc[36];
    #pragma unroll
    for (int i = 0; i < 36; i++) acc[i] = 0.f;

    for (int hd = 0; hd < 5; hd++) {
        __syncthreads();
        for (int idx = tid; idx < 36 * 256; idx += 256) {
            int i = idx >> 8, c = idx & 255;
            sh[i][c] = h[(size_t)(b * NOBJ + i) * 2560 + hd * 512 + coff + c];
        }
        if (tid < 36) {
            ss[tid] = als[(size_t)(b * NOBJ + tid) * 5 + hd];
            sd[tid] = ald[(size_t)(b * NOBJ + tid) * 5 + hd];
        }
        __syncthreads();
        if (tid < 36) softmax36(ss, sd, aT, tid);
        __syncthreads();

        const int c = tid;
        #pragma unroll 4
        for (int j = 0; j < 36; j++) {
            float hv = sh[j][c];
            #pragma unroll
            for (int it = 0; it < 9; it++) {
                float4 a = *(const float4*)&aT[j][it * 4];
                acc[it*4+0] = fmaf(a.x, hv, acc[it*4+0]);
                acc[it*4+1] = fmaf(a.y, hv, acc[it*4+1]);
                acc[it*4+2] = fmaf(a.z, hv, acc[it*4+2]);
                acc[it*4+3] = fmaf(a.w, hv, acc[it*4+3]);
            }
        }
    }

    float bv = bias[coff + tid];
    #pragma unroll 4
    for (int i = 0; i < 36; i++)
        out[(size_t)(b * NOBJ + i) * 512 + coff + tid] = acc[i] * 0.2f + bv;
}

// ==================== launch ====================
extern "C" void kernel_launch(void* const* d_in, const int* in_sizes, int n_in,
                              void* d_out, int out_size)
{
    const float* qe  = (const float*)d_in[0];
    const float* obj = (const float*)d_in[1];
    const float* Wq  = (const float*)d_in[3];
    const float* bq  = (const float*)d_in[4];
    const float* Wv  = (const float*)d_in[5];
    const float* bv  = (const float*)d_in[6];
    const float* W1  = (const float*)d_in[7];
    const float* a1s = (const float*)d_in[8];
    const float* a1d = (const float*)d_in[9];
    const float* b1  = (const float*)d_in[10];
    const float* W2  = (const float*)d_in[11];
    const float* a2s = (const float*)d_in[12];
    const float* a2d = (const float*)d_in[13];
    const float* b2  = (const float*)d_in[14];
    const float* W3  = (const float*)d_in[15];
    const float* a3s = (const float*)d_in[16];
    const float* a3d = (const float*)d_in[17];
    const float* b3  = (const float*)d_in[18];
    float* out = (float*)d_out;

    fp16 *qe16,*ob16,*WqT,*WvT,*W1T,*W2T,*W3T,*x16,*g116,*g216;
    float *q,*qpart,*h,*g1,*g2,*als,*ald;
    cudaGetSymbolAddress((void**)&qe16, g_qe16); cudaGetSymbolAddress((void**)&ob16, g_ob16);
    cudaGetSymbolAddress((void**)&WqT,  g_WqT);  cudaGetSymbolAddress((void**)&WvT,  g_WvT);
    cudaGetSymbolAddress((void**)&W1T,  g_W1T);  cudaGetSymbolAddress((void**)&W2T,  g_W2T);
    cudaGetSymbolAddress((void**)&W3T,  g_W3T);
    cudaGetSymbolAddress((void**)&x16,  g_x16);
    cudaGetSymbolAddress((void**)&g116, g_g116); cudaGetSymbolAddress((void**)&g216, g_g216);
    cudaGetSymbolAddress((void**)&q,    g_q);    cudaGetSymbolAddress((void**)&qpart,g_qpart);
    cudaGetSymbolAddress((void**)&h,    g_h);
    cudaGetSymbolAddress((void**)&g1,   g_g1);   cudaGetSymbolAddress((void**)&g2,   g_g2);
    cudaGetSymbolAddress((void**)&als,  g_als);  cudaGetSymbolAddress((void**)&ald,  g_ald);

    cudaFuncSetAttribute(gemm1, cudaFuncAttributeMaxDynamicSharedMemorySize, GEMM_SMEM);

    // conversions / weight prep
    conv16_k<<<(128 * (QDP/4) + 255) / 256, 256>>>(qe, qe16, 128, QD, QDP);
    conv16_k<<<(NNODE * (2048/4) + 255) / 256, 256>>>(obj, ob16, NNODE, 2048, 2048);
    tconv_k<<<dim3(2048/32, QDP/32), 256>>>(Wq, WqT, QD, 2048, QDP);
    tconv_k<<<dim3(2048/32, 2048/32), 256>>>(Wv, WvT, 2048, 2048, 2048);
    tconv_k<<<dim3(1024/32, 2048/32), 256>>>(W1, W1T, 2048, 1024, 2048);
    tconv_k<<<dim3(1024/32, 1024/32), 256>>>(W2, W2T, 1024, 1024, 1024);
    tconv_k<<<dim3(2560/32, 1024/32), 256>>>(W3, W3T, 1024, 2560, 1024);

    // q = qe @ Wq (split-K 8) + bq       grid 8 x 1 x 8 = 64 CTAs
    gemm1<<<dim3(8, 1, 8), 512, GEMM_SMEM>>>(qe16, WqT, 2048, QDP, 38, 5,
                                             nullptr, nullptr, qpart, nullptr, 0,
                                             (size_t)128 * 2048);
    combq_k<<<(128 * 2048 + 255) / 256, 256>>>(qpart, bq, q);

    // x = (obj @ Wv + bv) * q  -> fp16   grid 8 x 36
    gemm1<<<dim3(8, 36, 1), 512, GEMM_SMEM>>>(ob16, WvT, 2048, 2048, 32, 32,
                                              bv, q, nullptr, x16, 2, 0);

    // layer 1                            grid 4 x 36
    gemm1<<<dim3(4, 36, 1), 512, GEMM_SMEM>>>(x16, W1T, 1024, 2048, 32, 32,
                                              nullptr, nullptr, h, nullptr, 0, 0);
    al_k<<<(NNODE * 4 * 32 + 255) / 256, 256>>>(h, a1s, a1d, als, ald, NNODE * 4, 4, 256);
    gat_agg256<<<BATCH * 4, 256>>>(h, als, ald, b1, nullptr, g1, g116, 4);

    // layer 2 (+residual)                grid 4 x 36
    gemm1<<<dim3(4, 36, 1), 512, GEMM_SMEM>>>(g116, W2T, 1024, 1024, 16, 16,
                                              nullptr, nullptr, h, nullptr, 0, 0);
    al_k<<<(NNODE * 4 * 32 + 255) / 256, 256>>>(h, a2s, a2d, als, ald, NNODE * 4, 4, 256);
    gat_agg256<<<BATCH * 4, 256>>>(h, als, ald, b2, g1, g2, g216, 4);

    // layer 3 (mean over 5 heads)        grid 10 x 36
    gemm1<<<dim3(10, 36, 1), 512, GEMM_SMEM>>>(g216, W3T, 2560, 1024, 16, 16,
                                               nullptr, nullptr, h, nullptr, 0, 0);
    al_k<<<(NNODE * 5 * 32 + 255) / 256, 256>>>(h, a3s, a3d, als, ald, NNODE * 5, 5, 512);
    gat_mean_k<<<dim3(BATCH, 2), 256>>>(h, als, ald, b3, out);

    (void)in_sizes; (void)n_in; (void)out_size;
}

// round 9
// speedup vs baseline: 1.5463x; 1.0668x over previous
#include <cuda_runtime.h>
#include <cuda_fp16.h>
#include <math.h>
#include <stdint.h>

// Problem constants
#define BATCH 128
#define NOBJ  36
#define NNODE (BATCH*NOBJ)   // 4608
#define QD    2400
#define QDP   2432

typedef __half fp16;

#define SWZ128(o) ((o) ^ (((o) >> 3) & 0x70))

__device__ __forceinline__ uint32_t smem_u32(const void* p) {
    uint32_t a;
    asm("{ .reg .u64 t; cvta.to.shared.u64 t, %1; cvt.u32.u64 %0, t; }" : "=r"(a) : "l"(p));
    return a;
}
__device__ __forceinline__ void cpa16(uint32_t s, const void* g) {
    asm volatile("cp.async.cg.shared.global [%0], [%1], 16;" :: "r"(s), "l"(g));
}
#define CP_COMMIT() asm volatile("cp.async.commit_group;" ::: "memory")
#define CP_WAIT1()  asm volatile("cp.async.wait_group 1;" ::: "memory")
#define CP_WAIT0()  asm volatile("cp.async.wait_group 0;" ::: "memory")

__device__ __forceinline__ void ldmx4(uint32_t& r0, uint32_t& r1, uint32_t& r2, uint32_t& r3, uint32_t addr) {
    asm volatile("ldmatrix.sync.aligned.m8n8.x4.shared.b16 {%0,%1,%2,%3}, [%4];"
                 : "=r"(r0), "=r"(r1), "=r"(r2), "=r"(r3) : "r"(addr));
}
__device__ __forceinline__ void mma16816(float* c, const uint32_t* a, uint32_t b0, uint32_t b1) {
    asm volatile(
        "mma.sync.aligned.m16n8k16.row.col.f32.f16.f16.f32 "
        "{%0,%1,%2,%3}, {%4,%5,%6,%7}, {%8,%9}, {%0,%1,%2,%3};"
        : "+f"(c[0]), "+f"(c[1]), "+f"(c[2]), "+f"(c[3])
        : "r"(a[0]), "r"(a[1]), "r"(a[2]), "r"(a[3]), "r"(b0), "r"(b1));
}

// ==================== scratch (no allocations allowed) ====================
__device__ __align__(128) fp16 g_qe16[128 * QDP];
__device__ __align__(128) fp16 g_ob16[NNODE * 2048];
__device__ __align__(128) fp16 g_WqT [2048 * QDP];
__device__ __align__(128) fp16 g_WvT [2048 * 2048];
__device__ __align__(128) fp16 g_W1T [1024 * 2048];
__device__ __align__(128) fp16 g_W2T [1024 * 1024];
__device__ __align__(128) fp16 g_W3T [2560 * 1024];
__device__ __align__(128) fp16 g_x16 [NNODE * 2048];
__device__ __align__(128) fp16 g_g116[NNODE * 1024];
__device__ __align__(128) fp16 g_g216[NNODE * 1024];

__device__ float g_q    [128 * 2048];
__device__ float g_qpart[8 * 128 * 2048];
__device__ float g_h    [NNODE * 2560];
__device__ float g_g1   [NNODE * 1024];
__device__ float g_g2   [NNODE * 1024];
__device__ float g_als  [NNODE * 5];
__device__ float g_ald  [NNODE * 5];

// ==================== conversion kernels ====================
__global__ void conv16_k(const float* __restrict__ in, fp16* __restrict__ o16, int R, int C, int Cp)
{
    int idx = blockIdx.x * blockDim.x + threadIdx.x;
    int cq = Cp >> 2;
    if (idx >= R * cq) return;
    int r = idx / cq;
    int c4 = (idx - r * cq) * 4;
    float4 v = make_float4(0.f, 0.f, 0.f, 0.f);
    if (c4 < C) v = *(const float4*)(in + (size_t)r * C + c4);
    *(__half2*)(o16 + (size_t)r * Cp + c4)     = __floats2half2_rn(v.x, v.y);
    *(__half2*)(o16 + (size_t)r * Cp + c4 + 2) = __floats2half2_rn(v.z, v.w);
}

// transpose + fp16 convert: W fp32 [K,N] -> WT fp16 [N,Kp]
__global__ __launch_bounds__(256) void tconv_k(const float* __restrict__ W,
                                               fp16* __restrict__ WT,
                                               int K, int N, int Kp)
{
    __shared__ float t[32][33];
    int n0 = blockIdx.x * 32, k0 = blockIdx.y * 32;
    int tx = threadIdx.x & 31, ty = threadIdx.x >> 5;
    #pragma unroll
    for (int i = 0; i < 4; i++) {
        int k = k0 + ty + i * 8;
        t[ty + i * 8][tx] = (k < K) ? W[(size_t)k * N + n0 + tx] : 0.f;
    }
    __syncthreads();
    #pragma unroll
    for (int i = 0; i < 4; i++) {
        int n = n0 + ty + i * 8;
        WT[(size_t)n * Kp + k0 + tx] = __float2half_rn(t[tx][ty + i * 8]);
    }
}

// zero two float arrays (for L3 atomic al accumulation)
__global__ void zero2_k(float* __restrict__ a, float* __restrict__ b, int n)
{
    int idx = blockIdx.x * blockDim.x + threadIdx.x;
    if (idx < n) { a[idx] = 0.f; b[idx] = 0.f; }
}

// combine split-K 8 q partials + bias
__global__ void combq_k(const float* __restrict__ parts, const float* __restrict__ bq, float* __restrict__ q)
{
    int idx = blockIdx.x * blockDim.x + threadIdx.x;
    if (idx >= 128 * 2048) return;
    const size_t S = (size_t)128 * 2048;
    int c = idx & 2047;
    float s = bq[c];
    #pragma unroll
    for (int p = 0; p < 8; p++) s += parts[idx + p * S];
    q[idx] = s;
}

// ==================== fp16 GEMM + fused attention logits ====================
// C[M,N] = A[M,Kp] @ B[N,Kp]^T ; CTA tile 128x256, KC=64, 512 threads
// 16 warps in 4x4 grid, warp tile 32x64
// mode 0: Cf[splitStride*z + row*N+col] = acc
// mode 2: C16[row*N+col] = fp16((acc + bias[col]) * qmul[(row/36)*N+col])
// alMode 0: none; 1: als/ald direct store (CTA covers full head, C=alC);
//           2: als/ald global atomicAdd (CTA covers part of a head)
#define KC 64
#define BUFSZ 49152u          // A 16K + B 32K
#define GEMM_SMEM (2*BUFSZ + 1024)

__global__ __launch_bounds__(512, 1) void gemm1(
    const fp16* __restrict__ A, const fp16* __restrict__ B,
    int N, int Kp, int kcTotal, int kcPerSplit,
    const float* __restrict__ bias, const float* __restrict__ qmul,
    float* __restrict__ Cf, fp16* __restrict__ C16,
    int mode, size_t splitStride,
    const float* __restrict__ a_s, const float* __restrict__ a_d,
    float* __restrict__ als, float* __restrict__ ald,
    int alMode, int alH, int alC)
{
    extern __shared__ char dsm[];
    __shared__ float s_al[2][128];
    uint32_t sb = smem_u32(dsm);
    sb = (sb + 1023u) & ~1023u;

    const int tid = threadIdx.x;
    const int wid = tid >> 5;
    const int L   = tid & 31;
    const int m0 = blockIdx.y * 128;
    const int n0 = blockIdx.x * 256;
    const int kc0 = blockIdx.z * kcPerSplit;
    int kc1 = kc0 + kcPerSplit; if (kc1 > kcTotal) kc1 = kcTotal;
    const int ncl = kc1 - kc0;

    const int wm = (wid & 3) * 32;     // 4 warp-rows
    const int wn = (wid >> 2) * 64;    // 4 warp-cols

    float acc[2][8][4];
    #pragma unroll
    for (int i = 0; i < 2; i++)
        #pragma unroll
        for (int j = 0; j < 8; j++)
            #pragma unroll
            for (int k = 0; k < 4; k++) acc[i][j][k] = 0.f;

    // ldmatrix per-lane addressing (SW128 over 128B rows)
    const int rA = ((L >> 3) & 1) * 8 + (L & 7);
    const int cA = (L >> 4) * 16;
    const int rB = (L >> 4) * 8 + (L & 7);
    const int cB = ((L >> 3) & 1) * 16;

    uint32_t offA[2], mskA[2];
    #pragma unroll
    for (int mf = 0; mf < 2; mf++) {
        int row = wm + mf * 16 + rA;
        offA[mf] = (uint32_t)(row * 128);
        mskA[mf] = (uint32_t)((row & 7) * 16);
    }
    uint32_t offB[4], mskB[4];
    #pragma unroll
    for (int nf2 = 0; nf2 < 4; nf2++) {
        int row = wn + nf2 * 16 + rB;
        offB[nf2] = (uint32_t)(row * 128);
        mskB[nf2] = (uint32_t)((row & 7) * 16);
    }

    // layout per buffer: A @0 (16KB), B @16K (32KB)
    auto load_chunk = [&](int c, int s) {
        const int k0 = c * KC;
        uint32_t base = sb + (uint32_t)s * BUFSZ;
        #pragma unroll
        for (int i = 0; i < 2; i++) {
            int u = tid + i * 512;
            int r = u >> 3, uc = u & 7;
            uint32_t so = SWZ128((uint32_t)(r * 128 + uc * 16));
            cpa16(base + so, A + (size_t)(m0 + r) * Kp + k0 + uc * 8);
        }
        #pragma unroll
        for (int i = 0; i < 4; i++) {
            int u = tid + i * 512;
            int r = u >> 3, uc = u & 7;
            uint32_t so = SWZ128((uint32_t)(r * 128 + uc * 16));
            cpa16(base + 16384u + so, B + (size_t)(n0 + r) * Kp + k0 + uc * 8);
        }
    };

    load_chunk(kc0, 0); CP_COMMIT();

    for (int cc = 0; cc < ncl; cc++) {
        if (cc + 1 < ncl) {
            load_chunk(kc0 + cc + 1, (cc + 1) & 1);
            CP_COMMIT();
            CP_WAIT1();
        } else {
            CP_WAIT0();
        }
        __syncthreads();

        uint32_t base = sb + (uint32_t)(cc & 1) * BUFSZ;
        #pragma unroll
        for (int ks = 0; ks < 4; ks++) {
            const uint32_t kb = (uint32_t)(ks * 32);
            uint32_t af[2][4];
            #pragma unroll
            for (int mf = 0; mf < 2; mf++) {
                uint32_t rel = offA[mf] + ((kb + cA) ^ mskA[mf]);
                ldmx4(af[mf][0], af[mf][1], af[mf][2], af[mf][3], base + rel);
            }
            #pragma unroll
            for (int nf2 = 0; nf2 < 4; nf2++) {
                uint32_t rel = offB[nf2] + ((kb + cB) ^ mskB[nf2]);
                uint32_t bf[4];
                ldmx4(bf[0], bf[1], bf[2], bf[3], base + 16384u + rel);
                #pragma unroll
                for (int mf = 0; mf < 2; mf++) {
                    mma16816(acc[mf][nf2*2],   af[mf], bf[0], bf[1]);
                    mma16816(acc[mf][nf2*2+1], af[mf], bf[2], bf[3]);
                }
            }
        }
        __syncthreads();
    }

    // ---- epilogue: store C ----
    const int rEp = (L >> 2);
    const int cEp = (L & 3) * 2;
    #pragma unroll
    for (int mf = 0; mf < 2; mf++) {
        #pragma unroll
        for (int half = 0; half < 2; half++) {
            int row = m0 + wm + mf * 16 + rEp + half * 8;
            if (mode == 0) {
                float* dst = Cf + splitStride * blockIdx.z + (size_t)row * N;
                #pragma unroll
                for (int nf = 0; nf < 8; nf++) {
                    int col = n0 + wn + nf * 8 + cEp;
                    float2 v;
                    v.x = acc[mf][nf][half*2 + 0];
                    v.y = acc[mf][nf][half*2 + 1];
                    *(float2*)(dst + col) = v;
                }
            } else {  // mode 2: hadamard, write fp16
                const float* qrow = qmul + (size_t)(row / NOBJ) * N;
                fp16* d16 = C16 + (size_t)row * N;
                #pragma unroll
                for (int nf = 0; nf < 8; nf++) {
                    int col = n0 + wn + nf * 8 + cEp;
                    float o0 = (acc[mf][nf][half*2+0] + bias[col])   * qrow[col];
                    float o1 = (acc[mf][nf][half*2+1] + bias[col+1]) * qrow[col+1];
                    *(__half2*)(d16 + col) = __floats2half2_rn(o0, o1);
                }
            }
        }
    }

    // ---- fused attention logits ----
    if (alMode) {
        if (tid < 128) { s_al[0][tid] = 0.f; s_al[1][tid] = 0.f; }
        __syncthreads();
        const int hd = n0 / alC;
        const int chBase = (n0 % alC) + wn + cEp;
        float asr[16], adr[16];
        #pragma unroll
        for (int nf = 0; nf < 8; nf++) {
            #pragma unroll
            for (int j = 0; j < 2; j++) {
                int ch = chBase + nf * 8 + j;
                asr[nf*2+j] = a_s[(size_t)hd * alC + ch];
                adr[nf*2+j] = a_d[(size_t)hd * alC + ch];
            }
        }
        #pragma unroll
        for (int mf = 0; mf < 2; mf++) {
            #pragma unroll
            for (int half = 0; half < 2; half++) {
                float ps = 0.f, pd = 0.f;
                #pragma unroll
                for (int nf = 0; nf < 8; nf++) {
                    #pragma unroll
                    for (int j = 0; j < 2; j++) {
                        float v = acc[mf][nf][half*2 + j];
                        ps = fmaf(v, asr[nf*2+j], ps);
                        pd = fmaf(v, adr[nf*2+j], pd);
                    }
                }
                ps += __shfl_xor_sync(0xffffffffu, ps, 1);
                ps += __shfl_xor_sync(0xffffffffu, ps, 2);
                pd += __shfl_xor_sync(0xffffffffu, pd, 1);
                pd += __shfl_xor_sync(0xffffffffu, pd, 2);
                if ((L & 3) == 0) {
                    int r = wm + mf * 16 + rEp + half * 8;
                    atomicAdd(&s_al[0][r], ps);
                    atomicAdd(&s_al[1][r], pd);
                }
            }
        }
        __syncthreads();
        if (tid < 128) {
            size_t oi = (size_t)(m0 + tid) * alH + hd;
            if (alMode == 1) {
                als[oi] = s_al[0][tid];
                ald[oi] = s_al[1][tid];
            } else {
                atomicAdd(&als[oi], s_al[0][tid]);
                atomicAdd(&ald[oi], s_al[1][tid]);
            }
        }
    }
}

// ==================== softmax helper ====================
__device__ __forceinline__ void softmax36(const float* ss, const float* sd,
                                          float (*aT)[40], int i)
{
    float di = sd[i];
    float ev[36];
    float m = -3.4e38f;
    #pragma unroll
    for (int j = 0; j < 36; j++) {
        float e = ss[j] + di;
        e = (e > 0.f) ? e : 0.2f * e;
        ev[j] = e;
        m = fmaxf(m, e);
    }
    float sum = 0.f;
    #pragma unroll
    for (int j = 0; j < 36; j++) { float x = expf(ev[j] - m); ev[j] = x; sum += x; }
    float inv = 1.0f / (sum + 1e-16f);
    #pragma unroll
    for (int j = 0; j < 36; j++) aT[j][i] = ev[j] * inv;
}

// GAT aggregation C=256 concat + relu (+residual), write fp32 + fp16
__global__ __launch_bounds__(256) void gat_agg256(
    const float* __restrict__ h, const float* __restrict__ als, const float* __restrict__ ald,
    const float* __restrict__ bias, const float* __restrict__ resid,
    float* __restrict__ out, fp16* __restrict__ out16, int H)
{
    __shared__ float sh[36][256];
    __shared__ float aT[36][40];
    __shared__ float ss[36], sd[36];

    const int bh = blockIdx.x;
    const int b = bh / H, hd = bh - b * H;
    const int tid = threadIdx.x;
    const int stride = H * 256;
    const float* hbase = h + (size_t)(b * NOBJ) * stride + hd * 256;

    for (int idx = tid; idx < 36 * 64; idx += 256) {
        int i = idx >> 6, c4 = (idx & 63) * 4;
        float4 v = *(const float4*)(hbase + (size_t)i * stride + c4);
        *(float4*)&sh[i][c4] = v;
    }
    if (tid < 36) {
        ss[tid] = als[(size_t)(b * NOBJ + tid) * H + hd];
        sd[tid] = ald[(size_t)(b * NOBJ + tid) * H + hd];
    }
    __syncthreads();
    if (tid < 36) softmax36(ss, sd, aT, tid);
    __syncthreads();

    const int c = tid;
    float acc[36];
    #pragma unroll
    for (int i = 0; i < 36; i++) acc[i] = 0.f;

    #pragma unroll 4
    for (int j = 0; j < 36; j++) {
        float hv = sh[j][c];
        #pragma unroll
        for (int it = 0; it < 9; it++) {
            float4 a = *(const float4*)&aT[j][it * 4];
            acc[it*4+0] = fmaf(a.x, hv, acc[it*4+0]);
            acc[it*4+1] = fmaf(a.y, hv, acc[it*4+1]);
            acc[it*4+2] = fmaf(a.z, hv, acc[it*4+2]);
            acc[it*4+3] = fmaf(a.w, hv, acc[it*4+3]);
        }
    }

    float bv = bias[hd * 256 + c];
    #pragma unroll 4
    for (int i = 0; i < 36; i++) {
        size_t oi = (size_t)(b * NOBJ + i) * stride + hd * 256 + c;
        float o = fmaxf(acc[i] + bv, 0.f);
        if (resid) o += resid[oi];
        out[oi] = o;
        out16[oi] = __float2half_rn(o);
    }
}

// GAT layer 3: C=512, H=5, mean over heads + b3
__global__ __launch_bounds__(256) void gat_mean_k(
    const float* __restrict__ h, const float* __restrict__ als, const float* __restrict__ ald,
    const float* __restrict__ bias, float* __restrict__ out)
{
    __shared__ float sh[36][256];
    __shared__ float aT[36][40];
    __shared__ float ss[36], sd[36];

    const int b = blockIdx.x;
    const int coff = blockIdx.y * 256;
    const int tid = threadIdx.x;

    float acc[36];
    #pragma unroll
    for (int i = 0; i < 36; i++) acc[i] = 0.f;

    for (int hd = 0; hd < 5; hd++) {
        __syncthreads();
        for (int idx = tid; idx < 36 * 64; idx += 256) {
            int i = idx >> 6, c4 = (idx & 63) * 4;
            float4 v = *(const float4*)(h + (size_t)(b * NOBJ + i) * 2560 + hd * 512 + coff + c4);
            *(float4*)&sh[i][c4] = v;
        }
        if (tid < 36) {
            ss[tid] = als[(size_t)(b * NOBJ + tid) * 5 + hd];
            sd[tid] = ald[(size_t)(b * NOBJ + tid) * 5 + hd];
        }
        __syncthreads();
        if (tid < 36) softmax36(ss, sd, aT, tid);
        __syncthreads();

        const int c = tid;
        #pragma unroll 4
        for (int j = 0; j < 36; j++) {
            float hv = sh[j][c];
            #pragma unroll
            for (int it = 0; it < 9; it++) {
                float4 a = *(const float4*)&aT[j][it * 4];
                acc[it*4+0] = fmaf(a.x, hv, acc[it*4+0]);
                acc[it*4+1] = fmaf(a.y, hv, acc[it*4+1]);
                acc[it*4+2] = fmaf(a.z, hv, acc[it*4+2]);
                acc[it*4+3] = fmaf(a.w, hv, acc[it*4+3]);
            }
        }
    }

    float bv = bias[coff + tid];
    #pragma unroll 4
    for (int i = 0; i < 36; i++)
        out[(size_t)(b * NOBJ + i) * 512 + coff + tid] = acc[i] * 0.2f + bv;
}

// ==================== launch ====================
extern "C" void kernel_launch(void* const* d_in, const int* in_sizes, int n_in,
                              void* d_out, int out_size)
{
    const float* qe  = (const float*)d_in[0];
    const float* obj = (const float*)d_in[1];
    const float* Wq  = (const float*)d_in[3];
    const float* bq  = (const float*)d_in[4];
    const float* Wv  = (const float*)d_in[5];
    const float* bv  = (const float*)d_in[6];
    const float* W1  = (const float*)d_in[7];
    const float* a1s = (const float*)d_in[8];
    const float* a1d = (const float*)d_in[9];
    const float* b1  = (const float*)d_in[10];
    const float* W2  = (const float*)d_in[11];
    const float* a2s = (const float*)d_in[12];
    const float* a2d = (const float*)d_in[13];
    const float* b2  = (const float*)d_in[14];
    const float* W3  = (const float*)d_in[15];
    const float* a3s = (const float*)d_in[16];
    const float* a3d = (const float*)d_in[17];
    const float* b3  = (const float*)d_in[18];
    float* out = (float*)d_out;

    fp16 *qe16,*ob16,*WqT,*WvT,*W1T,*W2T,*W3T,*x16,*g116,*g216;
    float *q,*qpart,*h,*g1,*g2,*als,*ald;
    cudaGetSymbolAddress((void**)&qe16, g_qe16); cudaGetSymbolAddress((void**)&ob16, g_ob16);
    cudaGetSymbolAddress((void**)&WqT,  g_WqT);  cudaGetSymbolAddress((void**)&WvT,  g_WvT);
    cudaGetSymbolAddress((void**)&W1T,  g_W1T);  cudaGetSymbolAddress((void**)&W2T,  g_W2T);
    cudaGetSymbolAddress((void**)&W3T,  g_W3T);
    cudaGetSymbolAddress((void**)&x16,  g_x16);
    cudaGetSymbolAddress((void**)&g116, g_g116); cudaGetSymbolAddress((void**)&g216, g_g216);
    cudaGetSymbolAddress((void**)&q,    g_q);    cudaGetSymbolAddress((void**)&qpart,g_qpart);
    cudaGetSymbolAddress((void**)&h,    g_h);
    cudaGetSymbolAddress((void**)&g1,   g_g1);   cudaGetSymbolAddress((void**)&g2,   g_g2);
    cudaGetSymbolAddress((void**)&als,  g_als);  cudaGetSymbolAddress((void**)&ald,  g_ald);

    cudaFuncSetAttribute(gemm1, cudaFuncAttributeMaxDynamicSharedMemorySize, GEMM_SMEM);

    // conversions / weight prep
    conv16_k<<<(128 * (QDP/4) + 255) / 256, 256>>>(qe, qe16, 128, QD, QDP);
    conv16_k<<<(NNODE * (2048/4) + 255) / 256, 256>>>(obj, ob16, NNODE, 2048, 2048);
    tconv_k<<<dim3(2048/32, QDP/32), 256>>>(Wq, WqT, QD, 2048, QDP);
    tconv_k<<<dim3(2048/32, 2048/32), 256>>>(Wv, WvT, 2048, 2048, 2048);
    tconv_k<<<dim3(1024/32, 2048/32), 256>>>(W1, W1T, 2048, 1024, 2048);
    tconv_k<<<dim3(1024/32, 1024/32), 256>>>(W2, W2T, 1024, 1024, 1024);
    tconv_k<<<dim3(2560/32, 1024/32), 256>>>(W3, W3T, 1024, 2560, 1024);

    // q = qe @ Wq (split-K 8) + bq
    gemm1<<<dim3(8, 1, 8), 512, GEMM_SMEM>>>(qe16, WqT, 2048, QDP, 38, 5,
                                             nullptr, nullptr, qpart, nullptr, 0,
                                             (size_t)128 * 2048,
                                             nullptr, nullptr, nullptr, nullptr, 0, 1, 1);
    combq_k<<<(128 * 2048 + 255) / 256, 256>>>(qpart, bq, q);

    // x = (obj @ Wv + bv) * q  -> fp16
    gemm1<<<dim3(8, 36, 1), 512, GEMM_SMEM>>>(ob16, WvT, 2048, 2048, 32, 32,
                                              bv, q, nullptr, x16, 2, 0,
                                              nullptr, nullptr, nullptr, nullptr, 0, 1, 1);

    // layer 1 (al fused: H=4, C=256, direct)
    gemm1<<<dim3(4, 36, 1), 512, GEMM_SMEM>>>(x16, W1T, 1024, 2048, 32, 32,
                                              nullptr, nullptr, h, nullptr, 0, 0,
                                              a1s, a1d, als, ald, 1, 4, 256);
    gat_agg256<<<BATCH * 4, 256>>>(h, als, ald, b1, nullptr, g1, g116, 4);

    // layer 2 (+residual; al fused)
    gemm1<<<dim3(4, 36, 1), 512, GEMM_SMEM>>>(g116, W2T, 1024, 1024, 16, 16,
                                              nullptr, nullptr, h, nullptr, 0, 0,
                                              a2s, a2d, als, ald, 1, 4, 256);
    gat_agg256<<<BATCH * 4, 256>>>(h, als, ald, b2, g1, g2, g216, 4);

    // layer 3 (al fused with atomics; zero first)
    zero2_k<<<(NNODE * 5 + 255) / 256, 256>>>(als, ald, NNODE * 5);
    gemm1<<<dim3(10, 36, 1), 512, GEMM_SMEM>>>(g216, W3T, 2560, 1024, 16, 16,
                                               nullptr, nullptr, h, nullptr, 0, 0,
                                               a3s, a3d, als, ald, 2, 5, 512);
    gat_mean_k<<<dim3(BATCH, 2), 256>>>(h, als, ald, b3, out);

    (void)in_sizes; (void)n_in; (void)out_size;
}

// round 10
// speedup vs baseline: 1.5828x; 1.0236x over previous
#include <cuda_runtime.h>
#include <cuda_fp16.h>
#include <math.h>
#include <stdint.h>

// Problem constants
#define BATCH 128
#define NOBJ  36
#define NNODE (BATCH*NOBJ)   // 4608
#define QD    2400
#define QDP   2432

typedef __half fp16;

#define SWZ128(o) ((o) ^ (((o) >> 3) & 0x70))

__device__ __forceinline__ uint32_t smem_u32(const void* p) {
    uint32_t a;
    asm("{ .reg .u64 t; cvta.to.shared.u64 t, %1; cvt.u32.u64 %0, t; }" : "=r"(a) : "l"(p));
    return a;
}
__device__ __forceinline__ void cpa16(uint32_t s, const void* g) {
    asm volatile("cp.async.cg.shared.global [%0], [%1], 16;" :: "r"(s), "l"(g));
}
#define CP_COMMIT() asm volatile("cp.async.commit_group;" ::: "memory")
#define CP_WAIT1()  asm volatile("cp.async.wait_group 1;" ::: "memory")
#define CP_WAIT0()  asm volatile("cp.async.wait_group 0;" ::: "memory")

__device__ __forceinline__ void ldmx4(uint32_t& r0, uint32_t& r1, uint32_t& r2, uint32_t& r3, uint32_t addr) {
    asm volatile("ldmatrix.sync.aligned.m8n8.x4.shared.b16 {%0,%1,%2,%3}, [%4];"
                 : "=r"(r0), "=r"(r1), "=r"(r2), "=r"(r3) : "r"(addr));
}
__device__ __forceinline__ void mma16816(float* c, const uint32_t* a, uint32_t b0, uint32_t b1) {
    asm volatile(
        "mma.sync.aligned.m16n8k16.row.col.f32.f16.f16.f32 "
        "{%0,%1,%2,%3}, {%4,%5,%6,%7}, {%8,%9}, {%0,%1,%2,%3};"
        : "+f"(c[0]), "+f"(c[1]), "+f"(c[2]), "+f"(c[3])
        : "r"(a[0]), "r"(a[1]), "r"(a[2]), "r"(a[3]), "r"(b0), "r"(b1));
}

// ==================== scratch (no allocations allowed) ====================
__device__ __align__(128) fp16 g_qe16[128 * QDP];
__device__ __align__(128) fp16 g_ob16[NNODE * 2048];
__device__ __align__(128) fp16 g_WqT [2048 * QDP];
__device__ __align__(128) fp16 g_WvT [2048 * 2048];
__device__ __align__(128) fp16 g_W1T [1024 * 2048];
__device__ __align__(128) fp16 g_W2T [1024 * 1024];
__device__ __align__(128) fp16 g_W3T [2560 * 1024];
__device__ __align__(128) fp16 g_x16 [NNODE * 2048];
__device__ __align__(128) fp16 g_h16 [NNODE * 2560];
__device__ __align__(128) fp16 g_g116[NNODE * 1024];
__device__ __align__(128) fp16 g_g216[NNODE * 1024];

__device__ float g_q    [128 * 2048];
__device__ float g_qpart[8 * 128 * 2048];
__device__ float g_als  [NNODE * 5];
__device__ float g_ald  [NNODE * 5];

// ==================== conversion kernels ====================
// fp32 [R,C] -> fp16 [R,Cp]; 16 elems per thread
__global__ __launch_bounds__(256) void conv16_k(const float* __restrict__ in, fp16* __restrict__ o16,
                                                int R, int C, int Cp)
{
    int g = blockIdx.x * blockDim.x + threadIdx.x;
    int cq = Cp >> 4;
    if (g >= R * cq) return;
    int r = g / cq;
    int c16 = (g - r * cq) * 16;
    const float* src = in + (size_t)r * C + c16;
    fp16* dst = o16 + (size_t)r * Cp + c16;
    __half2 o[8];
    #pragma unroll
    for (int j = 0; j < 4; j++) {
        float4 v = make_float4(0.f, 0.f, 0.f, 0.f);
        if (c16 + j * 4 < C) v = *(const float4*)(src + j * 4);
        o[j*2+0] = __floats2half2_rn(v.x, v.y);
        o[j*2+1] = __floats2half2_rn(v.z, v.w);
    }
    *(uint4*)(dst)     = *(uint4*)&o[0];
    *(uint4*)(dst + 8) = *(uint4*)&o[4];
}

// transpose + fp16 convert: W fp32 [K,N] -> WT fp16 [N,Kp]; 64x64 tiles
__global__ __launch_bounds__(256) void tconv_k(const float* __restrict__ W,
                                               fp16* __restrict__ WT,
                                               int K, int N, int Kp)
{
    __shared__ float t[64][65];
    const int n0 = blockIdx.x * 64, k0 = blockIdx.y * 64;
    const int tid = threadIdx.x;
    // load 64 k-rows x 64 n-cols, float4
    {
        int tx = tid & 15, ty = tid >> 4;       // 16x16
        #pragma unroll
        for (int i = 0; i < 4; i++) {
            int k = k0 + ty + i * 16;
            float4 v = make_float4(0.f, 0.f, 0.f, 0.f);
            if (k < K) v = *(const float4*)(W + (size_t)k * N + n0 + tx * 4);
            t[ty + i * 16][tx*4+0] = v.x;
            t[ty + i * 16][tx*4+1] = v.y;
            t[ty + i * 16][tx*4+2] = v.z;
            t[ty + i * 16][tx*4+3] = v.w;
        }
    }
    __syncthreads();
    // write 64 n-rows x 64 k-cols fp16; 4 threads per n-row, 16 halves each
    {
        int nr = tid >> 2;                       // 0..63
        int kq = (tid & 3) * 16;                 // 0,16,32,48
        __half2 o[8];
        #pragma unroll
        for (int j = 0; j < 8; j++)
            o[j] = __floats2half2_rn(t[kq + j*2][nr], t[kq + j*2 + 1][nr]);
        fp16* dst = WT + (size_t)(n0 + nr) * Kp + k0 + kq;
        *(uint4*)(dst)     = *(uint4*)&o[0];
        *(uint4*)(dst + 8) = *(uint4*)&o[4];
    }
}

// zero two float arrays (for L3 atomic al accumulation)
__global__ void zero2_k(float* __restrict__ a, float* __restrict__ b, int n)
{
    int idx = blockIdx.x * blockDim.x + threadIdx.x;
    if (idx < n) { a[idx] = 0.f; b[idx] = 0.f; }
}

// combine split-K 8 q partials + bias
__global__ void combq_k(const float* __restrict__ parts, const float* __restrict__ bq, float* __restrict__ q)
{
    int idx = blockIdx.x * blockDim.x + threadIdx.x;
    if (idx >= 128 * 2048) return;
    const size_t S = (size_t)128 * 2048;
    int c = idx & 2047;
    float s = bq[c];
    #pragma unroll
    for (int p = 0; p < 8; p++) s += parts[idx + p * S];
    q[idx] = s;
}

// ==================== fp16 GEMM + fused attention logits ====================
// C[M,N] = A[M,Kp] @ B[N,Kp]^T ; CTA tile 128x256, KC=64, 512 threads
// mode 0: Cf[splitStride*z + row*N+col] = acc  (fp32, split-K)
// mode 1: C16[row*N+col] = fp16(acc)
// mode 2: C16[row*N+col] = fp16((acc + bias[col]) * qmul[(row/36)*N+col])
// alMode 0: none; 1: als/ald direct store; 2: als/ald global atomicAdd
#define KC 64
#define BUFSZ 49152u          // A 16K + B 32K
#define GEMM_SMEM (2*BUFSZ + 1024)

__global__ __launch_bounds__(512, 1) void gemm1(
    const fp16* __restrict__ A, const fp16* __restrict__ B,
    int N, int Kp, int kcTotal, int kcPerSplit,
    const float* __restrict__ bias, const float* __restrict__ qmul,
    float* __restrict__ Cf, fp16* __restrict__ C16,
    int mode, size_t splitStride,
    const float* __restrict__ a_s, const float* __restrict__ a_d,
    float* __restrict__ als, float* __restrict__ ald,
    int alMode, int alH, int alC)
{
    extern __shared__ char dsm[];
    __shared__ float s_al[2][128];
    uint32_t sb = smem_u32(dsm);
    sb = (sb + 1023u) & ~1023u;

    const int tid = threadIdx.x;
    const int wid = tid >> 5;
    const int L   = tid & 31;
    const int m0 = blockIdx.y * 128;
    const int n0 = blockIdx.x * 256;
    const int kc0 = blockIdx.z * kcPerSplit;
    int kc1 = kc0 + kcPerSplit; if (kc1 > kcTotal) kc1 = kcTotal;
    const int ncl = kc1 - kc0;

    const int wm = (wid & 3) * 32;     // 4 warp-rows
    const int wn = (wid >> 2) * 64;    // 4 warp-cols

    float acc[2][8][4];
    #pragma unroll
    for (int i = 0; i < 2; i++)
        #pragma unroll
        for (int j = 0; j < 8; j++)
            #pragma unroll
            for (int k = 0; k < 4; k++) acc[i][j][k] = 0.f;

    const int rA = ((L >> 3) & 1) * 8 + (L & 7);
    const int cA = (L >> 4) * 16;
    const int rB = (L >> 4) * 8 + (L & 7);
    const int cB = ((L >> 3) & 1) * 16;

    uint32_t offA[2], mskA[2];
    #pragma unroll
    for (int mf = 0; mf < 2; mf++) {
        int row = wm + mf * 16 + rA;
        offA[mf] = (uint32_t)(row * 128);
        mskA[mf] = (uint32_t)((row & 7) * 16);
    }
    uint32_t offB[4], mskB[4];
    #pragma unroll
    for (int nf2 = 0; nf2 < 4; nf2++) {
        int row = wn + nf2 * 16 + rB;
        offB[nf2] = (uint32_t)(row * 128);
        mskB[nf2] = (uint32_t)((row & 7) * 16);
    }

    auto load_chunk = [&](int c, int s) {
        const int k0 = c * KC;
        uint32_t base = sb + (uint32_t)s * BUFSZ;
        #pragma unroll
        for (int i = 0; i < 2; i++) {
            int u = tid + i * 512;
            int r = u >> 3, uc = u & 7;
            uint32_t so = SWZ128((uint32_t)(r * 128 + uc * 16));
            cpa16(base + so, A + (size_t)(m0 + r) * Kp + k0 + uc * 8);
        }
        #pragma unroll
        for (int i = 0; i < 4; i++) {
            int u = tid + i * 512;
            int r = u >> 3, uc = u & 7;
            uint32_t so = SWZ128((uint32_t)(r * 128 + uc * 16));
            cpa16(base + 16384u + so, B + (size_t)(n0 + r) * Kp + k0 + uc * 8);
        }
    };

    load_chunk(kc0, 0); CP_COMMIT();

    for (int cc = 0; cc < ncl; cc++) {
        if (cc + 1 < ncl) {
            load_chunk(kc0 + cc + 1, (cc + 1) & 1);
            CP_COMMIT();
            CP_WAIT1();
        } else {
            CP_WAIT0();
        }
        __syncthreads();

        uint32_t base = sb + (uint32_t)(cc & 1) * BUFSZ;
        #pragma unroll
        for (int ks = 0; ks < 4; ks++) {
            const uint32_t kb = (uint32_t)(ks * 32);
            uint32_t af[2][4];
            #pragma unroll
            for (int mf = 0; mf < 2; mf++) {
                uint32_t rel = offA[mf] + ((kb + cA) ^ mskA[mf]);
                ldmx4(af[mf][0], af[mf][1], af[mf][2], af[mf][3], base + rel);
            }
            #pragma unroll
            for (int nf2 = 0; nf2 < 4; nf2++) {
                uint32_t rel = offB[nf2] + ((kb + cB) ^ mskB[nf2]);
                uint32_t bf[4];
                ldmx4(bf[0], bf[1], bf[2], bf[3], base + 16384u + rel);
                #pragma unroll
                for (int mf = 0; mf < 2; mf++) {
                    mma16816(acc[mf][nf2*2],   af[mf], bf[0], bf[1]);
                    mma16816(acc[mf][nf2*2+1], af[mf], bf[2], bf[3]);
                }
            }
        }
        __syncthreads();
    }

    // ---- epilogue: store C ----
    const int rEp = (L >> 2);
    const int cEp = (L & 3) * 2;
    #pragma unroll
    for (int mf = 0; mf < 2; mf++) {
        #pragma unroll
        for (int half = 0; half < 2; half++) {
            int row = m0 + wm + mf * 16 + rEp + half * 8;
            if (mode == 0) {
                float* dst = Cf + splitStride * blockIdx.z + (size_t)row * N;
                #pragma unroll
                for (int nf = 0; nf < 8; nf++) {
                    int col = n0 + wn + nf * 8 + cEp;
                    float2 v;
                    v.x = acc[mf][nf][half*2 + 0];
                    v.y = acc[mf][nf][half*2 + 1];
                    *(float2*)(dst + col) = v;
                }
            } else if (mode == 1) {   // plain fp16 store
                fp16* d16 = C16 + (size_t)row * N;
                #pragma unroll
                for (int nf = 0; nf < 8; nf++) {
                    int col = n0 + wn + nf * 8 + cEp;
                    *(__half2*)(d16 + col) =
                        __floats2half2_rn(acc[mf][nf][half*2+0], acc[mf][nf][half*2+1]);
                }
            } else {  // mode 2: hadamard, write fp16
                const float* qrow = qmul + (size_t)(row / NOBJ) * N;
                fp16* d16 = C16 + (size_t)row * N;
                #pragma unroll
                for (int nf = 0; nf < 8; nf++) {
                    int col = n0 + wn + nf * 8 + cEp;
                    float o0 = (acc[mf][nf][half*2+0] + bias[col])   * qrow[col];
                    float o1 = (acc[mf][nf][half*2+1] + bias[col+1]) * qrow[col+1];
                    *(__half2*)(d16 + col) = __floats2half2_rn(o0, o1);
                }
            }
        }
    }

    // ---- fused attention logits (from exact fp32 accumulators) ----
    if (alMode) {
        if (tid < 128) { s_al[0][tid] = 0.f; s_al[1][tid] = 0.f; }
        __syncthreads();
        const int hd = n0 / alC;
        const int chBase = (n0 % alC) + wn + cEp;
        float asr[16], adr[16];
        #pragma unroll
        for (int nf = 0; nf < 8; nf++) {
            #pragma unroll
            for (int j = 0; j < 2; j++) {
                int ch = chBase + nf * 8 + j;
                asr[nf*2+j] = a_s[(size_t)hd * alC + ch];
                adr[nf*2+j] = a_d[(size_t)hd * alC + ch];
            }
        }
        #pragma unroll
        for (int mf = 0; mf < 2; mf++) {
            #pragma unroll
            for (int half = 0; half < 2; half++) {
                float ps = 0.f, pd = 0.f;
                #pragma unroll
                for (int nf = 0; nf < 8; nf++) {
                    #pragma unroll
                    for (int j = 0; j < 2; j++) {
                        float v = acc[mf][nf][half*2 + j];
                        ps = fmaf(v, asr[nf*2+j], ps);
                        pd = fmaf(v, adr[nf*2+j], pd);
                    }
                }
                ps += __shfl_xor_sync(0xffffffffu, ps, 1);
                ps += __shfl_xor_sync(0xffffffffu, ps, 2);
                pd += __shfl_xor_sync(0xffffffffu, pd, 1);
                pd += __shfl_xor_sync(0xffffffffu, pd, 2);
                if ((L & 3) == 0) {
                    int r = wm + mf * 16 + rEp + half * 8;
                    atomicAdd(&s_al[0][r], ps);
                    atomicAdd(&s_al[1][r], pd);
                }
            }
        }
        __syncthreads();
        if (tid < 128) {
            size_t oi = (size_t)(m0 + tid) * alH + hd;
            if (alMode == 1) {
                als[oi] = s_al[0][tid];
                ald[oi] = s_al[1][tid];
            } else {
                atomicAdd(&als[oi], s_al[0][tid]);
                atomicAdd(&ald[oi], s_al[1][tid]);
            }
        }
    }
}

// ==================== softmax helper ====================
__device__ __forceinline__ void softmax36(const float* ss, const float* sd,
                                          float (*aT)[40], int i)
{
    float di = sd[i];
    float ev[36];
    float m = -3.4e38f;
    #pragma unroll
    for (int j = 0; j < 36; j++) {
        float e = ss[j] + di;
        e = (e > 0.f) ? e : 0.2f * e;
        ev[j] = e;
        m = fmaxf(m, e);
    }
    float sum = 0.f;
    #pragma unroll
    for (int j = 0; j < 36; j++) { float x = expf(ev[j] - m); ev[j] = x; sum += x; }
    float inv = 1.0f / (sum + 1e-16f);
    #pragma unroll
    for (int j = 0; j < 36; j++) aT[j][i] = ev[j] * inv;
}

// GAT aggregation C=256 concat + relu (+fp16 residual), all-fp16 I/O
__global__ __launch_bounds__(256) void gat_agg256(
    const fp16* __restrict__ h16, const float* __restrict__ als, const float* __restrict__ ald,
    const float* __restrict__ bias, const fp16* __restrict__ resid16,
    fp16* __restrict__ out16, int H)
{
    __shared__ float sh[36][256];
    __shared__ float aT[36][40];
    __shared__ float ss[36], sd[36];

    const int bh = blockIdx.x;
    const int b = bh / H, hd = bh - b * H;
    const int tid = threadIdx.x;
    const int stride = H * 256;
    const fp16* hbase = h16 + (size_t)(b * NOBJ) * stride + hd * 256;

    for (int idx = tid; idx < 36 * 32; idx += 256) {
        int i = idx >> 5, c8 = (idx & 31) * 8;
        uint4 raw = *(const uint4*)(hbase + (size_t)i * stride + c8);
        const __half2* hp = (const __half2*)&raw;
        #pragma unroll
        for (int j = 0; j < 4; j++) {
            float2 f = __half22float2(hp[j]);
            sh[i][c8 + j*2]     = f.x;
            sh[i][c8 + j*2 + 1] = f.y;
        }
    }
    if (tid < 36) {
        ss[tid] = als[(size_t)(b * NOBJ + tid) * H + hd];
        sd[tid] = ald[(size_t)(b * NOBJ + tid) * H + hd];
    }
    __syncthreads();
    if (tid < 36) softmax36(ss, sd, aT, tid);
    __syncthreads();

    const int c = tid;
    float acc[36];
    #pragma unroll
    for (int i = 0; i < 36; i++) acc[i] = 0.f;

    #pragma unroll 4
    for (int j = 0; j < 36; j++) {
        float hv = sh[j][c];
        #pragma unroll
        for (int it = 0; it < 9; it++) {
            float4 a = *(const float4*)&aT[j][it * 4];
            acc[it*4+0] = fmaf(a.x, hv, acc[it*4+0]);
            acc[it*4+1] = fmaf(a.y, hv, acc[it*4+1]);
            acc[it*4+2] = fmaf(a.z, hv, acc[it*4+2]);
            acc[it*4+3] = fmaf(a.w, hv, acc[it*4+3]);
        }
    }

    float bv = bias[hd * 256 + c];
    #pragma unroll 4
    for (int i = 0; i < 36; i++) {
        size_t oi = (size_t)(b * NOBJ + i) * stride + hd * 256 + c;
        float o = fmaxf(acc[i] + bv, 0.f);
        if (resid16) o += __half2float(resid16[oi]);
        out16[oi] = __float2half_rn(o);
    }
}

// GAT layer 3: C=512, H=5, mean over heads + b3, fp16 input, fp32 output
__global__ __launch_bounds__(256) void gat_mean_k(
    const fp16* __restrict__ h16, const float* __restrict__ als, const float* __restrict__ ald,
    const float* __restrict__ bias, float* __restrict__ out)
{
    __shared__ float sh[36][256];
    __shared__ float aT[36][40];
    __shared__ float ss[36], sd[36];

    const int b = blockIdx.x;
    const int coff = blockIdx.y * 256;
    const int tid = threadIdx.x;

    float acc[36];
    #pragma unroll
    for (int i = 0; i < 36; i++) acc[i] = 0.f;

    for (int hd = 0; hd < 5; hd++) {
        __syncthreads();
        for (int idx = tid; idx < 36 * 32; idx += 256) {
            int i = idx >> 5, c8 = (idx & 31) * 8;
            uint4 raw = *(const uint4*)(h16 + (size_t)(b * NOBJ + i) * 2560 + hd * 512 + coff + c8);
            const __half2* hp = (const __half2*)&raw;
            #pragma unroll
            for (int j = 0; j < 4; j++) {
                float2 f = __half22float2(hp[j]);
                sh[i][c8 + j*2]     = f.x;
                sh[i][c8 + j*2 + 1] = f.y;
            }
        }
        if (tid < 36) {
            ss[tid] = als[(size_t)(b * NOBJ + tid) * 5 + hd];
            sd[tid] = ald[(size_t)(b * NOBJ + tid) * 5 + hd];
        }
        __syncthreads();
        if (tid < 36) softmax36(ss, sd, aT, tid);
        __syncthreads();

        const int c = tid;
        #pragma unroll 4
        for (int j = 0; j < 36; j++) {
            float hv = sh[j][c];
            #pragma unroll
            for (int it = 0; it < 9; it++) {
                float4 a = *(const float4*)&aT[j][it * 4];
                acc[it*4+0] = fmaf(a.x, hv, acc[it*4+0]);
                acc[it*4+1] = fmaf(a.y, hv, acc[it*4+1]);
                acc[it*4+2] = fmaf(a.z, hv, acc[it*4+2]);
                acc[it*4+3] = fmaf(a.w, hv, acc[it*4+3]);
            }
        }
    }

    float bv = bias[coff + tid];
    #pragma unroll 4
    for (int i = 0; i < 36; i++)
        out[(size_t)(b * NOBJ + i) * 512 + coff + tid] = acc[i] * 0.2f + bv;
}

// ==================== launch ====================
extern "C" void kernel_launch(void* const* d_in, const int* in_sizes, int n_in,
                              void* d_out, int out_size)
{
    const float* qe  = (const float*)d_in[0];
    const float* obj = (const float*)d_in[1];
    const float* Wq  = (const float*)d_in[3];
    const float* bq  = (const float*)d_in[4];
    const float* Wv  = (const float*)d_in[5];
    const float* bv  = (const float*)d_in[6];
    const float* W1  = (const float*)d_in[7];
    const float* a1s = (const float*)d_in[8];
    const float* a1d = (const float*)d_in[9];
    const float* b1  = (const float*)d_in[10];
    const float* W2  = (const float*)d_in[11];
    const float* a2s = (const float*)d_in[12];
    const float* a2d = (const float*)d_in[13];
    const float* b2  = (const float*)d_in[14];
    const float* W3  = (const float*)d_in[15];
    const float* a3s = (const float*)d_in[16];
    const float* a3d = (const float*)d_in[17];
    const float* b3  = (const float*)d_in[18];
    float* out = (float*)d_out;

    fp16 *qe16,*ob16,*WqT,*WvT,*W1T,*W2T,*W3T,*x16,*h16,*g116,*g216;
    float *q,*qpart,*als,*ald;
    cudaGetSymbolAddress((void**)&qe16, g_qe16); cudaGetSymbolAddress((void**)&ob16, g_ob16);
    cudaGetSymbolAddress((void**)&WqT,  g_WqT);  cudaGetSymbolAddress((void**)&WvT,  g_WvT);
    cudaGetSymbolAddress((void**)&W1T,  g_W1T);  cudaGetSymbolAddress((void**)&W2T,  g_W2T);
    cudaGetSymbolAddress((void**)&W3T,  g_W3T);
    cudaGetSymbolAddress((void**)&x16,  g_x16);  cudaGetSymbolAddress((void**)&h16,  g_h16);
    cudaGetSymbolAddress((void**)&g116, g_g116); cudaGetSymbolAddress((void**)&g216, g_g216);
    cudaGetSymbolAddress((void**)&q,    g_q);    cudaGetSymbolAddress((void**)&qpart,g_qpart);
    cudaGetSymbolAddress((void**)&als,  g_als);  cudaGetSymbolAddress((void**)&ald,  g_ald);

    cudaFuncSetAttribute(gemm1, cudaFuncAttributeMaxDynamicSharedMemorySize, GEMM_SMEM);

    // conversions / weight prep
    conv16_k<<<(128 * (QDP/16) + 255) / 256, 256>>>(qe, qe16, 128, QD, QDP);
    conv16_k<<<(NNODE * (2048/16) + 255) / 256, 256>>>(obj, ob16, NNODE, 2048, 2048);
    tconv_k<<<dim3(2048/64, QDP/64), 256>>>(Wq, WqT, QD, 2048, QDP);
    tconv_k<<<dim3(2048/64, 2048/64), 256>>>(Wv, WvT, 2048, 2048, 2048);
    tconv_k<<<dim3(1024/64, 2048/64), 256>>>(W1, W1T, 2048, 1024, 2048);
    tconv_k<<<dim3(1024/64, 1024/64), 256>>>(W2, W2T, 1024, 1024, 1024);
    tconv_k<<<dim3(2560/64, 1024/64), 256>>>(W3, W3T, 1024, 2560, 1024);

    // q = qe @ Wq (split-K 8) + bq
    gemm1<<<dim3(8, 1, 8), 512, GEMM_SMEM>>>(qe16, WqT, 2048, QDP, 38, 5,
                                             nullptr, nullptr, qpart, nullptr, 0,
                                             (size_t)128 * 2048,
                                             nullptr, nullptr, nullptr, nullptr, 0, 1, 1);
    combq_k<<<(128 * 2048 + 255) / 256, 256>>>(qpart, bq, q);

    // x = (obj @ Wv + bv) * q  -> fp16
    gemm1<<<dim3(8, 36, 1), 512, GEMM_SMEM>>>(ob16, WvT, 2048, 2048, 32, 32,
                                              bv, q, nullptr, x16, 2, 0,
                                              nullptr, nullptr, nullptr, nullptr, 0, 1, 1);

    // layer 1 (h fp16, al fused: H=4, C=256, direct)
    gemm1<<<dim3(4, 36, 1), 512, GEMM_SMEM>>>(x16, W1T, 1024, 2048, 32, 32,
                                              nullptr, nullptr, nullptr, h16, 1, 0,
                                              a1s, a1d, als, ald, 1, 4, 256);
    gat_agg256<<<BATCH * 4, 256>>>(h16, als, ald, b1, nullptr, g116, 4);

    // layer 2 (+fp16 residual; al fused)
    gemm1<<<dim3(4, 36, 1), 512, GEMM_SMEM>>>(g116, W2T, 1024, 1024, 16, 16,
                                              nullptr, nullptr, nullptr, h16, 1, 0,
                                              a2s, a2d, als, ald, 1, 4, 256);
    gat_agg256<<<BATCH * 4, 256>>>(h16, als, ald, b2, g116, g216, 4);

    // layer 3 (al fused with atomics; zero first)
    zero2_k<<<(NNODE * 5 + 255) / 256, 256>>>(als, ald, NNODE * 5);
    gemm1<<<dim3(10, 36, 1), 512, GEMM_SMEM>>>(g216, W3T, 2560, 1024, 16, 16,
                                               nullptr, nullptr, nullptr, h16, 1, 0,
                                               a3s, a3d, als, ald, 2, 5, 512);
    gat_mean_k<<<dim3(BATCH, 2), 256>>>(h16, als, ald, b3, out);

    (void)in_sizes; (void)n_in; (void)out_size;
}

// round 11
// speedup vs baseline: 1.6254x; 1.0269x over previous
#include <cuda_runtime.h>
#include <cuda_fp16.h>
#include <math.h>
#include <stdint.h>

// Problem constants
#define BATCH 128
#define NOBJ  36
#define NNODE (BATCH*NOBJ)   // 4608
#define QD    2400
#define QDP   2432

typedef __half fp16;

#define SWZ128(o) ((o) ^ (((o) >> 3) & 0x70))

__device__ __forceinline__ uint32_t smem_u32(const void* p) {
    uint32_t a;
    asm("{ .reg .u64 t; cvta.to.shared.u64 t, %1; cvt.u32.u64 %0, t; }" : "=r"(a) : "l"(p));
    return a;
}
__device__ __forceinline__ void cpa16(uint32_t s, const void* g) {
    asm volatile("cp.async.cg.shared.global [%0], [%1], 16;" :: "r"(s), "l"(g));
}
#define CP_COMMIT() asm volatile("cp.async.commit_group;" ::: "memory")
#define CP_WAIT1()  asm volatile("cp.async.wait_group 1;" ::: "memory")
#define CP_WAIT0()  asm volatile("cp.async.wait_group 0;" ::: "memory")

__device__ __forceinline__ void ldmx4(uint32_t& r0, uint32_t& r1, uint32_t& r2, uint32_t& r3, uint32_t addr) {
    asm volatile("ldmatrix.sync.aligned.m8n8.x4.shared.b16 {%0,%1,%2,%3}, [%4];"
                 : "=r"(r0), "=r"(r1), "=r"(r2), "=r"(r3) : "r"(addr));
}
__device__ __forceinline__ void mma16816(float* c, const uint32_t* a, uint32_t b0, uint32_t b1) {
    asm volatile(
        "mma.sync.aligned.m16n8k16.row.col.f32.f16.f16.f32 "
        "{%0,%1,%2,%3}, {%4,%5,%6,%7}, {%8,%9}, {%0,%1,%2,%3};"
        : "+f"(c[0]), "+f"(c[1]), "+f"(c[2]), "+f"(c[3])
        : "r"(a[0]), "r"(a[1]), "r"(a[2]), "r"(a[3]), "r"(b0), "r"(b1));
}

// ==================== scratch (no allocations allowed) ====================
__device__ __align__(128) fp16 g_qe16[128 * QDP];
__device__ __align__(128) fp16 g_ob16[NNODE * 2048];
__device__ __align__(128) fp16 g_WqT [2048 * QDP];
__device__ __align__(128) fp16 g_WvT [2048 * 2048];
__device__ __align__(128) fp16 g_W1T [1024 * 2048];
__device__ __align__(128) fp16 g_W2T [1024 * 1024];
__device__ __align__(128) fp16 g_W3T [2560 * 1024];
__device__ __align__(128) fp16 g_x16 [NNODE * 2048];
__device__ __align__(128) fp16 g_h16 [NNODE * 2560];
__device__ __align__(128) fp16 g_g116[NNODE * 1024];
__device__ __align__(128) fp16 g_g216[NNODE * 1024];

__device__ float g_q    [128 * 2048];
__device__ float g_qpart[8 * 128 * 2048];
__device__ float g_als  [NNODE * 5];        // L1/L2 direct
__device__ float g_ald  [NNODE * 5];
__device__ float g_als2 [NNODE * 5 * 2];    // L3 partial (2 half-heads)
__device__ float g_ald2 [NNODE * 5 * 2];

// ==================== conversion kernels ====================
__global__ __launch_bounds__(256) void conv16_k(const float* __restrict__ in, fp16* __restrict__ o16,
                                                int R, int C, int Cp)
{
    int g = blockIdx.x * blockDim.x + threadIdx.x;
    int cq = Cp >> 4;
    if (g >= R * cq) return;
    int r = g / cq;
    int c16 = (g - r * cq) * 16;
    const float* src = in + (size_t)r * C + c16;
    fp16* dst = o16 + (size_t)r * Cp + c16;
    __half2 o[8];
    #pragma unroll
    for (int j = 0; j < 4; j++) {
        float4 v = make_float4(0.f, 0.f, 0.f, 0.f);
        if (c16 + j * 4 < C) v = *(const float4*)(src + j * 4);
        o[j*2+0] = __floats2half2_rn(v.x, v.y);
        o[j*2+1] = __floats2half2_rn(v.z, v.w);
    }
    *(uint4*)(dst)     = *(uint4*)&o[0];
    *(uint4*)(dst + 8) = *(uint4*)&o[4];
}

// batched transpose+convert for all 5 weights in one launch
struct WJob { const float* W; fp16* WT; int K, N, Kp, tStart, tX; };
struct WJobs { WJob j[5]; };

__global__ __launch_bounds__(256) void tconv_all(WJobs jobs)
{
    __shared__ float t[64][65];
    int b = blockIdx.x;
    int ji = 0;
    #pragma unroll
    for (int i = 1; i < 5; i++) if (b >= jobs.j[i].tStart) ji = i;
    const WJob jb = jobs.j[ji];
    int tt = b - jb.tStart;
    const int n0 = (tt % jb.tX) * 64;
    const int k0 = (tt / jb.tX) * 64;
    const int tid = threadIdx.x;
    {
        int tx = tid & 15, ty = tid >> 4;
        #pragma unroll
        for (int i = 0; i < 4; i++) {
            int k = k0 + ty + i * 16;
            float4 v = make_float4(0.f, 0.f, 0.f, 0.f);
            if (k < jb.K) v = *(const float4*)(jb.W + (size_t)k * jb.N + n0 + tx * 4);
            t[ty + i * 16][tx*4+0] = v.x;
            t[ty + i * 16][tx*4+1] = v.y;
            t[ty + i * 16][tx*4+2] = v.z;
            t[ty + i * 16][tx*4+3] = v.w;
        }
    }
    __syncthreads();
    {
        int nr = tid >> 2;
        int kq = (tid & 3) * 16;
        __half2 o[8];
        #pragma unroll
        for (int j = 0; j < 8; j++)
            o[j] = __floats2half2_rn(t[kq + j*2][nr], t[kq + j*2 + 1][nr]);
        fp16* dst = jb.WT + (size_t)(n0 + nr) * jb.Kp + k0 + kq;
        *(uint4*)(dst)     = *(uint4*)&o[0];
        *(uint4*)(dst + 8) = *(uint4*)&o[4];
    }
}

// combine split-K 8 q partials + bias
__global__ void combq_k(const float* __restrict__ parts, const float* __restrict__ bq, float* __restrict__ q)
{
    int idx = blockIdx.x * blockDim.x + threadIdx.x;
    if (idx >= 128 * 2048) return;
    const size_t S = (size_t)128 * 2048;
    int c = idx & 2047;
    float s = bq[c];
    #pragma unroll
    for (int p = 0; p < 8; p++) s += parts[idx + p * S];
    q[idx] = s;
}

// ==================== fp16 GEMM + fused attention logits ====================
// templated on M-tile rows (MR = 128 or 64); N-tile 256, KC=64, MR*4 threads
// mode 0: Cf[splitStride*z + row*N+col] = acc
// mode 1: C16 = fp16(acc)
// mode 2: C16 = fp16((acc + bias[col]) * qmul[(row/36)*N+col])
// alMode 0: none; 1: direct store to als/ald [node*alH+hd]
//        3: partial store to als/ald doubled buffer [(node*alH+hd)*2 + halfIdx]
#define KC 64

template<int MR>
__global__ __launch_bounds__(MR*4, 1) void gemm1(
    const fp16* __restrict__ A, const fp16* __restrict__ B,
    int N, int Kp, int kcTotal, int kcPerSplit,
    const float* __restrict__ bias, const float* __restrict__ qmul,
    float* __restrict__ Cf, fp16* __restrict__ C16,
    int mode, size_t splitStride,
    const float* __restrict__ a_s, const float* __restrict__ a_d,
    float* __restrict__ als, float* __restrict__ ald,
    int alMode, int alH, int alC)
{
    constexpr int THREADS = MR * 4;
    constexpr uint32_t ABYTES = (uint32_t)MR * 128u;
    constexpr uint32_t BUFSZ = ABYTES + 32768u;
    constexpr int MW = MR / 32;              // warp-rows

    extern __shared__ char dsm[];
    __shared__ float s_al[2][MR];
    uint32_t sb = smem_u32(dsm);
    sb = (sb + 1023u) & ~1023u;

    const int tid = threadIdx.x;
    const int wid = tid >> 5;
    const int L   = tid & 31;
    const int m0 = blockIdx.y * MR;
    const int n0 = blockIdx.x * 256;
    const int kc0 = blockIdx.z * kcPerSplit;
    int kc1 = kc0 + kcPerSplit; if (kc1 > kcTotal) kc1 = kcTotal;
    const int ncl = kc1 - kc0;

    const int wm = (wid % MW) * 32;
    const int wn = (wid / MW) * 64;

    float acc[2][8][4];
    #pragma unroll
    for (int i = 0; i < 2; i++)
        #pragma unroll
        for (int j = 0; j < 8; j++)
            #pragma unroll
            for (int k = 0; k < 4; k++) acc[i][j][k] = 0.f;

    const int rA = ((L >> 3) & 1) * 8 + (L & 7);
    const int cA = (L >> 4) * 16;
    const int rB = (L >> 4) * 8 + (L & 7);
    const int cB = ((L >> 3) & 1) * 16;

    uint32_t offA[2], mskA[2];
    #pragma unroll
    for (int mf = 0; mf < 2; mf++) {
        int row = wm + mf * 16 + rA;
        offA[mf] = (uint32_t)(row * 128);
        mskA[mf] = (uint32_t)((row & 7) * 16);
    }
    uint32_t offB[4], mskB[4];
    #pragma unroll
    for (int nf2 = 0; nf2 < 4; nf2++) {
        int row = wn + nf2 * 16 + rB;
        offB[nf2] = (uint32_t)(row * 128);
        mskB[nf2] = (uint32_t)((row & 7) * 16);
    }

    auto load_chunk = [&](int c, int s) {
        const int k0 = c * KC;
        uint32_t base = sb + (uint32_t)s * BUFSZ;
        #pragma unroll
        for (int i = 0; i < (MR * 8) / THREADS; i++) {
            int u = tid + i * THREADS;
            int r = u >> 3, uc = u & 7;
            uint32_t so = SWZ128((uint32_t)(r * 128 + uc * 16));
            cpa16(base + so, A + (size_t)(m0 + r) * Kp + k0 + uc * 8);
        }
        #pragma unroll
        for (int i = 0; i < 2048 / THREADS; i++) {
            int u = tid + i * THREADS;
            int r = u >> 3, uc = u & 7;
            uint32_t so = SWZ128((uint32_t)(r * 128 + uc * 16));
            cpa16(base + ABYTES + so, B + (size_t)(n0 + r) * Kp + k0 + uc * 8);
        }
    };

    load_chunk(kc0, 0); CP_COMMIT();

    for (int cc = 0; cc < ncl; cc++) {
        if (cc + 1 < ncl) {
            load_chunk(kc0 + cc + 1, (cc + 1) & 1);
            CP_COMMIT();
            CP_WAIT1();
        } else {
            CP_WAIT0();
        }
        __syncthreads();

        uint32_t base = sb + (uint32_t)(cc & 1) * BUFSZ;
        #pragma unroll
        for (int ks = 0; ks < 4; ks++) {
            const uint32_t kb = (uint32_t)(ks * 32);
            uint32_t af[2][4];
            #pragma unroll
            for (int mf = 0; mf < 2; mf++) {
                uint32_t rel = offA[mf] + ((kb + cA) ^ mskA[mf]);
                ldmx4(af[mf][0], af[mf][1], af[mf][2], af[mf][3], base + rel);
            }
            #pragma unroll
            for (int nf2 = 0; nf2 < 4; nf2++) {
                uint32_t rel = offB[nf2] + ((kb + cB) ^ mskB[nf2]);
                uint32_t bf[4];
                ldmx4(bf[0], bf[1], bf[2], bf[3], base + ABYTES + rel);
                #pragma unroll
                for (int mf = 0; mf < 2; mf++) {
                    mma16816(acc[mf][nf2*2],   af[mf], bf[0], bf[1]);
                    mma16816(acc[mf][nf2*2+1], af[mf], bf[2], bf[3]);
                }
            }
        }
        __syncthreads();
    }

    // ---- epilogue: store C ----
    const int rEp = (L >> 2);
    const int cEp = (L & 3) * 2;
    #pragma unroll
    for (int mf = 0; mf < 2; mf++) {
        #pragma unroll
        for (int half = 0; half < 2; half++) {
            int row = m0 + wm + mf * 16 + rEp + half * 8;
            if (mode == 0) {
                float* dst = Cf + splitStride * blockIdx.z + (size_t)row * N;
                #pragma unroll
                for (int nf = 0; nf < 8; nf++) {
                    int col = n0 + wn + nf * 8 + cEp;
                    float2 v;
                    v.x = acc[mf][nf][half*2 + 0];
                    v.y = acc[mf][nf][half*2 + 1];
                    *(float2*)(dst + col) = v;
                }
            } else if (mode == 1) {
                fp16* d16 = C16 + (size_t)row * N;
                #pragma unroll
                for (int nf = 0; nf < 8; nf++) {
                    int col = n0 + wn + nf * 8 + cEp;
                    *(__half2*)(d16 + col) =
                        __floats2half2_rn(acc[mf][nf][half*2+0], acc[mf][nf][half*2+1]);
                }
            } else {
                const float* qrow = qmul + (size_t)(row / NOBJ) * N;
                fp16* d16 = C16 + (size_t)row * N;
                #pragma unroll
                for (int nf = 0; nf < 8; nf++) {
                    int col = n0 + wn + nf * 8 + cEp;
                    float o0 = (acc[mf][nf][half*2+0] + bias[col])   * qrow[col];
                    float o1 = (acc[mf][nf][half*2+1] + bias[col+1]) * qrow[col+1];
                    *(__half2*)(d16 + col) = __floats2half2_rn(o0, o1);
                }
            }
        }
    }

    // ---- fused attention logits (from exact fp32 accumulators) ----
    if (alMode) {
        if (tid < MR) { s_al[0][tid] = 0.f; s_al[1][tid] = 0.f; }
        __syncthreads();
        const int hd = n0 / alC;
        const int chBase = (n0 % alC) + wn + cEp;
        float asr[16], adr[16];
        #pragma unroll
        for (int nf = 0; nf < 8; nf++) {
            #pragma unroll
            for (int j = 0; j < 2; j++) {
                int ch = chBase + nf * 8 + j;
                asr[nf*2+j] = a_s[(size_t)hd * alC + ch];
                adr[nf*2+j] = a_d[(size_t)hd * alC + ch];
            }
        }
        #pragma unroll
        for (int mf = 0; mf < 2; mf++) {
            #pragma unroll
            for (int half = 0; half < 2; half++) {
                float ps = 0.f, pd = 0.f;
                #pragma unroll
                for (int nf = 0; nf < 8; nf++) {
                    #pragma unroll
                    for (int j = 0; j < 2; j++) {
                        float v = acc[mf][nf][half*2 + j];
                        ps = fmaf(v, asr[nf*2+j], ps);
                        pd = fmaf(v, adr[nf*2+j], pd);
                    }
                }
                ps += __shfl_xor_sync(0xffffffffu, ps, 1);
                ps += __shfl_xor_sync(0xffffffffu, ps, 2);
                pd += __shfl_xor_sync(0xffffffffu, pd, 1);
                pd += __shfl_xor_sync(0xffffffffu, pd, 2);
                if ((L & 3) == 0) {
                    int r = wm + mf * 16 + rEp + half * 8;
                    atomicAdd(&s_al[0][r], ps);
                    atomicAdd(&s_al[1][r], pd);
                }
            }
        }
        __syncthreads();
        if (tid < MR) {
            if (alMode == 1) {
                size_t oi = (size_t)(m0 + tid) * alH + hd;
                als[oi] = s_al[0][tid];
                ald[oi] = s_al[1][tid];
            } else {  // alMode 3: partial half-head store
                int part = (n0 % alC) >> 8;   // 0 or 1 (alC=512)
                size_t oi = ((size_t)(m0 + tid) * alH + hd) * 2 + part;
                als[oi] = s_al[0][tid];
                ald[oi] = s_al[1][tid];
            }
        }
    }
}

// ==================== softmax helper ====================
__device__ __forceinline__ void softmax36(const float* ss, const float* sd,
                                          float (*aT)[40], int i)
{
    float di = sd[i];
    float ev[36];
    float m = -3.4e38f;
    #pragma unroll
    for (int j = 0; j < 36; j++) {
        float e = ss[j] + di;
        e = (e > 0.f) ? e : 0.2f * e;
        ev[j] = e;
        m = fmaxf(m, e);
    }
    float sum = 0.f;
    #pragma unroll
    for (int j = 0; j < 36; j++) { float x = expf(ev[j] - m); ev[j] = x; sum += x; }
    float inv = 1.0f / (sum + 1e-16f);
    #pragma unroll
    for (int j = 0; j < 36; j++) aT[j][i] = ev[j] * inv;
}

// GAT aggregation C=256 concat + relu (+fp16 residual), all-fp16 I/O
__global__ __launch_bounds__(256) void gat_agg256(
    const fp16* __restrict__ h16, const float* __restrict__ als, const float* __restrict__ ald,
    const float* __restrict__ bias, const fp16* __restrict__ resid16,
    fp16* __restrict__ out16, int H)
{
    __shared__ float sh[36][256];
    __shared__ float aT[36][40];
    __shared__ float ss[36], sd[36];

    const int bh = blockIdx.x;
    const int b = bh / H, hd = bh - b * H;
    const int tid = threadIdx.x;
    const int stride = H * 256;
    const fp16* hbase = h16 + (size_t)(b * NOBJ) * stride + hd * 256;

    for (int idx = tid; idx < 36 * 32; idx += 256) {
        int i = idx >> 5, c8 = (idx & 31) * 8;
        uint4 raw = *(const uint4*)(hbase + (size_t)i * stride + c8);
        const __half2* hp = (const __half2*)&raw;
        #pragma unroll
        for (int j = 0; j < 4; j++) {
            float2 f = __half22float2(hp[j]);
            sh[i][c8 + j*2]     = f.x;
            sh[i][c8 + j*2 + 1] = f.y;
        }
    }
    if (tid < 36) {
        ss[tid] = als[(size_t)(b * NOBJ + tid) * H + hd];
        sd[tid] = ald[(size_t)(b * NOBJ + tid) * H + hd];
    }
    __syncthreads();
    if (tid < 36) softmax36(ss, sd, aT, tid);
    __syncthreads();

    const int c = tid;
    float acc[36];
    #pragma unroll
    for (int i = 0; i < 36; i++) acc[i] = 0.f;

    #pragma unroll 4
    for (int j = 0; j < 36; j++) {
        float hv = sh[j][c];
        #pragma unroll
        for (int it = 0; it < 9; it++) {
            float4 a = *(const float4*)&aT[j][it * 4];
            acc[it*4+0] = fmaf(a.x, hv, acc[it*4+0]);
            acc[it*4+1] = fmaf(a.y, hv, acc[it*4+1]);
            acc[it*4+2] = fmaf(a.z, hv, acc[it*4+2]);
            acc[it*4+3] = fmaf(a.w, hv, acc[it*4+3]);
        }
    }

    float bv = bias[hd * 256 + c];
    #pragma unroll 4
    for (int i = 0; i < 36; i++) {
        size_t oi = (size_t)(b * NOBJ + i) * stride + hd * 256 + c;
        float o = fmaxf(acc[i] + bv, 0.f);
        if (resid16) o += __half2float(resid16[oi]);
        out16[oi] = __float2half_rn(o);
    }
}

// GAT layer 3: C=512, H=5, mean over heads + b3; logits from doubled partial buffers
__global__ __launch_bounds__(256) void gat_mean_k(
    const fp16* __restrict__ h16, const float* __restrict__ als2, const float* __restrict__ ald2,
    const float* __restrict__ bias, float* __restrict__ out)
{
    __shared__ float sh[36][256];
    __shared__ float aT[36][40];
    __shared__ float ss[36], sd[36];

    const int b = blockIdx.x;
    const int coff = blockIdx.y * 256;
    const int tid = threadIdx.x;

    float acc[36];
    #pragma unroll
    for (int i = 0; i < 36; i++) acc[i] = 0.f;

    for (int hd = 0; hd < 5; hd++) {
        __syncthreads();
        for (int idx = tid; idx < 36 * 32; idx += 256) {
            int i = idx >> 5, c8 = (idx & 31) * 8;
            uint4 raw = *(const uint4*)(h16 + (size_t)(b * NOBJ + i) * 2560 + hd * 512 + coff + c8);
            const __half2* hp = (const __half2*)&raw;
            #pragma unroll
            for (int j = 0; j < 4; j++) {
                float2 f = __half22float2(hp[j]);
                sh[i][c8 + j*2]     = f.x;
                sh[i][c8 + j*2 + 1] = f.y;
            }
        }
        if (tid < 36) {
            size_t base = ((size_t)(b * NOBJ + tid) * 5 + hd) * 2;
            ss[tid] = als2[base] + als2[base + 1];
            sd[tid] = ald2[base] + ald2[base + 1];
        }
        __syncthreads();
        if (tid < 36) softmax36(ss, sd, aT, tid);
        __syncthreads();

        const int c = tid;
        #pragma unroll 4
        for (int j = 0; j < 36; j++) {
            float hv = sh[j][c];
            #pragma unroll
            for (int it = 0; it < 9; it++) {
                float4 a = *(const float4*)&aT[j][it * 4];
                acc[it*4+0] = fmaf(a.x, hv, acc[it*4+0]);
                acc[it*4+1] = fmaf(a.y, hv, acc[it*4+1]);
                acc[it*4+2] = fmaf(a.z, hv, acc[it*4+2]);
                acc[it*4+3] = fmaf(a.w, hv, acc[it*4+3]);
            }
        }
    }

    float bv = bias[coff + tid];
    #pragma unroll 4
    for (int i = 0; i < 36; i++)
        out[(size_t)(b * NOBJ + i) * 512 + coff + tid] = acc[i] * 0.2f + bv;
}

// ==================== launch ====================
extern "C" void kernel_launch(void* const* d_in, const int* in_sizes, int n_in,
                              void* d_out, int out_size)
{
    const float* qe  = (const float*)d_in[0];
    const float* obj = (const float*)d_in[1];
    const float* Wq  = (const float*)d_in[3];
    const float* bq  = (const float*)d_in[4];
    const float* Wv  = (const float*)d_in[5];
    const float* bv  = (const float*)d_in[6];
    const float* W1  = (const float*)d_in[7];
    const float* a1s = (const float*)d_in[8];
    const float* a1d = (const float*)d_in[9];
    const float* b1  = (const float*)d_in[10];
    const float* W2  = (const float*)d_in[11];
    const float* a2s = (const float*)d_in[12];
    const float* a2d = (const float*)d_in[13];
    const float* b2  = (const float*)d_in[14];
    const float* W3  = (const float*)d_in[15];
    const float* a3s = (const float*)d_in[16];
    const float* a3d = (const float*)d_in[17];
    const float* b3  = (const float*)d_in[18];
    float* out = (float*)d_out;

    fp16 *qe16,*ob16,*WqT,*WvT,*W1T,*W2T,*W3T,*x16,*h16,*g116,*g216;
    float *q,*qpart,*als,*ald,*als2,*ald2;
    cudaGetSymbolAddress((void**)&qe16, g_qe16); cudaGetSymbolAddress((void**)&ob16, g_ob16);
    cudaGetSymbolAddress((void**)&WqT,  g_WqT);  cudaGetSymbolAddress((void**)&WvT,  g_WvT);
    cudaGetSymbolAddress((void**)&W1T,  g_W1T);  cudaGetSymbolAddress((void**)&W2T,  g_W2T);
    cudaGetSymbolAddress((void**)&W3T,  g_W3T);
    cudaGetSymbolAddress((void**)&x16,  g_x16);  cudaGetSymbolAddress((void**)&h16,  g_h16);
    cudaGetSymbolAddress((void**)&g116, g_g116); cudaGetSymbolAddress((void**)&g216, g_g216);
    cudaGetSymbolAddress((void**)&q,    g_q);    cudaGetSymbolAddress((void**)&qpart,g_qpart);
    cudaGetSymbolAddress((void**)&als,  g_als);  cudaGetSymbolAddress((void**)&ald,  g_ald);
    cudaGetSymbolAddress((void**)&als2, g_als2); cudaGetSymbolAddress((void**)&ald2, g_ald2);

    const int SMEM128 = 2 * (128 * 128 + 32768) + 1024;   // 99328
    const int SMEM64  = 2 * (64 * 128 + 32768) + 1024;    // 82944
    cudaFuncSetAttribute(gemm1<128>, cudaFuncAttributeMaxDynamicSharedMemorySize, SMEM128);
    cudaFuncSetAttribute(gemm1<64>,  cudaFuncAttributeMaxDynamicSharedMemorySize, SMEM64);

    // conversions
    conv16_k<<<(128 * (QDP/16) + 255) / 256, 256>>>(qe, qe16, 128, QD, QDP);
    conv16_k<<<(NNODE * (2048/16) + 255) / 256, 256>>>(obj, ob16, NNODE, 2048, 2048);

    // batched weight transpose+convert (5 jobs, one launch)
    {
        WJobs jobs;
        int cursor = 0;
        auto add = [&](int i, const float* W, fp16* WT, int K, int N, int Kp) {
            jobs.j[i] = { W, WT, K, N, Kp, cursor, N / 64 };
            cursor += (N / 64) * (Kp / 64);
        };
        add(0, Wq, WqT, QD,   2048, QDP);
        add(1, Wv, WvT, 2048, 2048, 2048);
        add(2, W1, W1T, 2048, 1024, 2048);
        add(3, W2, W2T, 1024, 1024, 1024);
        add(4, W3, W3T, 1024, 2560, 1024);
        tconv_all<<<cursor, 256>>>(jobs);
    }

    // q = qe @ Wq (split-K 8, M-tile 64) + bq     grid 8 x 2 x 8 = 128 CTAs
    gemm1<64><<<dim3(8, 2, 8), 256, SMEM64>>>(qe16, WqT, 2048, QDP, 38, 5,
                                              nullptr, nullptr, qpart, nullptr, 0,
                                              (size_t)128 * 2048,
                                              nullptr, nullptr, nullptr, nullptr, 0, 1, 1);
    combq_k<<<(128 * 2048 + 255) / 256, 256>>>(qpart, bq, q);

    // x = (obj @ Wv + bv) * q  -> fp16
    gemm1<128><<<dim3(8, 36, 1), 512, SMEM128>>>(ob16, WvT, 2048, 2048, 32, 32,
                                                 bv, q, nullptr, x16, 2, 0,
                                                 nullptr, nullptr, nullptr, nullptr, 0, 1, 1);

    // layer 1 (h fp16, al fused)
    gemm1<128><<<dim3(4, 36, 1), 512, SMEM128>>>(x16, W1T, 1024, 2048, 32, 32,
                                                 nullptr, nullptr, nullptr, h16, 1, 0,
                                                 a1s, a1d, als, ald, 1, 4, 256);
    gat_agg256<<<BATCH * 4, 256>>>(h16, als, ald, b1, nullptr, g116, 4);

    // layer 2 (+fp16 residual; al fused)
    gemm1<128><<<dim3(4, 36, 1), 512, SMEM128>>>(g116, W2T, 1024, 1024, 16, 16,
                                                 nullptr, nullptr, nullptr, h16, 1, 0,
                                                 a2s, a2d, als, ald, 1, 4, 256);
    gat_agg256<<<BATCH * 4, 256>>>(h16, als, ald, b2, g116, g216, 4);

    // layer 3 (M-tile 64 -> 720 CTAs; al partial direct store, no atomics/zeroing)
    gemm1<64><<<dim3(10, 72, 1), 256, SMEM64>>>(g216, W3T, 2560, 1024, 16, 16,
                                                nullptr, nullptr, nullptr, h16, 1, 0,
                                                a3s, a3d, als2, ald2, 3, 5, 512);
    gat_mean_k<<<dim3(BATCH, 2), 256>>>(h16, als2, ald2, b3, out);

    (void)in_sizes; (void)n_in; (void)out_size;
}

// round 12
// speedup vs baseline: 1.6614x; 1.0222x over previous
#include <cuda_runtime.h>
#include <cuda_fp16.h>
#include <math.h>
#include <stdint.h>

// Problem constants
#define BATCH 128
#define NOBJ  36
#define NNODE (BATCH*NOBJ)   // 4608
#define QD    2400
#define QDP   2432

typedef __half fp16;

#define SWZ128(o) ((o) ^ (((o) >> 3) & 0x70))

// Programmatic Dependent Launch controls (sm_90+ PTX, family-common)
#define PDL_TRIGGER() asm volatile("griddepcontrol.launch_dependents;" ::: "memory")
#define PDL_WAIT()    asm volatile("griddepcontrol.wait;" ::: "memory")

__device__ __forceinline__ uint32_t smem_u32(const void* p) {
    uint32_t a;
    asm("{ .reg .u64 t; cvta.to.shared.u64 t, %1; cvt.u32.u64 %0, t; }" : "=r"(a) : "l"(p));
    return a;
}
__device__ __forceinline__ void cpa16(uint32_t s, const void* g) {
    asm volatile("cp.async.cg.shared.global [%0], [%1], 16;" :: "r"(s), "l"(g));
}
#define CP_COMMIT() asm volatile("cp.async.commit_group;" ::: "memory")
#define CP_WAIT1()  asm volatile("cp.async.wait_group 1;" ::: "memory")
#define CP_WAIT0()  asm volatile("cp.async.wait_group 0;" ::: "memory")

__device__ __forceinline__ void ldmx4(uint32_t& r0, uint32_t& r1, uint32_t& r2, uint32_t& r3, uint32_t addr) {
    asm volatile("ldmatrix.sync.aligned.m8n8.x4.shared.b16 {%0,%1,%2,%3}, [%4];"
                 : "=r"(r0), "=r"(r1), "=r"(r2), "=r"(r3) : "r"(addr));
}
__device__ __forceinline__ void mma16816(float* c, const uint32_t* a, uint32_t b0, uint32_t b1) {
    asm volatile(
        "mma.sync.aligned.m16n8k16.row.col.f32.f16.f16.f32 "
        "{%0,%1,%2,%3}, {%4,%5,%6,%7}, {%8,%9}, {%0,%1,%2,%3};"
        : "+f"(c[0]), "+f"(c[1]), "+f"(c[2]), "+f"(c[3])
        : "r"(a[0]), "r"(a[1]), "r"(a[2]), "r"(a[3]), "r"(b0), "r"(b1));
}

// ==================== scratch (no allocations allowed) ====================
__device__ __align__(128) fp16 g_qe16[128 * QDP];
__device__ __align__(128) fp16 g_ob16[NNODE * 2048];
__device__ __align__(128) fp16 g_WqT [2048 * QDP];
__device__ __align__(128) fp16 g_WvT [2048 * 2048];
__device__ __align__(128) fp16 g_W1T [1024 * 2048];
__device__ __align__(128) fp16 g_W2T [1024 * 1024];
__device__ __align__(128) fp16 g_W3T [2560 * 1024];
__device__ __align__(128) fp16 g_x16 [NNODE * 2048];
__device__ __align__(128) fp16 g_h16 [NNODE * 2560];
__device__ __align__(128) fp16 g_g116[NNODE * 1024];
__device__ __align__(128) fp16 g_g216[NNODE * 1024];

__device__ float g_q    [128 * 2048];
__device__ float g_qpart[8 * 128 * 2048];
__device__ float g_als  [NNODE * 5];        // L1/L2 direct
__device__ float g_ald  [NNODE * 5];
__device__ float g_als2 [NNODE * 5 * 2];    // L3 partial (2 half-heads)
__device__ float g_ald2 [NNODE * 5 * 2];

// ==================== batched prep: convs + weight transposes ====================
// type 0: conv fp32[K rows, N cols] -> fp16[K, Kp] (pad)
// type 1: transpose+convert fp32[K,N] -> fp16[N,Kp]
struct PJob { const float* src; fp16* dst; int K, N, Kp, start, tX, type; };
struct PJobs { PJob j[7]; };

__global__ __launch_bounds__(256) void prep_all(PJobs jobs)
{
    __shared__ float t[64][65];
    PDL_TRIGGER();
    int b = blockIdx.x;
    int ji = 0;
    #pragma unroll
    for (int i = 1; i < 7; i++) if (b >= jobs.j[i].start) ji = i;
    const PJob jb = jobs.j[ji];
    const int tt = b - jb.start;
    const int tid = threadIdx.x;

    if (jb.type == 0) {
        int g = tt * 256 + tid;
        int cq = jb.Kp >> 4;
        if (g >= jb.K * cq) return;
        int r = g / cq;
        int c16 = (g - r * cq) * 16;
        const float* src = jb.src + (size_t)r * jb.N + c16;
        fp16* dst = jb.dst + (size_t)r * jb.Kp + c16;
        __half2 o[8];
        #pragma unroll
        for (int j = 0; j < 4; j++) {
            float4 v = make_float4(0.f, 0.f, 0.f, 0.f);
            if (c16 + j * 4 < jb.N) v = *(const float4*)(src + j * 4);
            o[j*2+0] = __floats2half2_rn(v.x, v.y);
            o[j*2+1] = __floats2half2_rn(v.z, v.w);
        }
        *(uint4*)(dst)     = *(uint4*)&o[0];
        *(uint4*)(dst + 8) = *(uint4*)&o[4];
    } else {
        const int n0 = (tt % jb.tX) * 64;
        const int k0 = (tt / jb.tX) * 64;
        {
            int tx = tid & 15, ty = tid >> 4;
            #pragma unroll
            for (int i = 0; i < 4; i++) {
                int k = k0 + ty + i * 16;
                float4 v = make_float4(0.f, 0.f, 0.f, 0.f);
                if (k < jb.K) v = *(const float4*)(jb.src + (size_t)k * jb.N + n0 + tx * 4);
                t[ty + i * 16][tx*4+0] = v.x;
                t[ty + i * 16][tx*4+1] = v.y;
                t[ty + i * 16][tx*4+2] = v.z;
                t[ty + i * 16][tx*4+3] = v.w;
            }
        }
        __syncthreads();
        {
            int nr = tid >> 2;
            int kq = (tid & 3) * 16;
            __half2 o[8];
            #pragma unroll
            for (int j = 0; j < 8; j++)
                o[j] = __floats2half2_rn(t[kq + j*2][nr], t[kq + j*2 + 1][nr]);
            fp16* dst = jb.dst + (size_t)(n0 + nr) * jb.Kp + k0 + kq;
            *(uint4*)(dst)     = *(uint4*)&o[0];
            *(uint4*)(dst + 8) = *(uint4*)&o[4];
        }
    }
}

// combine split-K 8 q partials + bias (PDL: early launch, wait for q gemm)
__global__ void combq_k(const float* __restrict__ parts, const float* __restrict__ bq, float* __restrict__ q)
{
    PDL_TRIGGER();
    PDL_WAIT();
    int idx = blockIdx.x * blockDim.x + threadIdx.x;
    if (idx >= 128 * 2048) return;
    const size_t S = (size_t)128 * 2048;
    int c = idx & 2047;
    float s = bq[c];
    #pragma unroll
    for (int p = 0; p < 8; p++) s += parts[idx + p * S];
    q[idx] = s;
}

// ==================== fp16 GEMM + fused attention logits ====================
// templated on M-tile rows (MR = 128 or 64); N-tile 256, KC=64, MR*4 threads
// mode 0: Cf[splitStride*z + row*N+col] = acc
// mode 1: C16 = fp16(acc)
// mode 2: C16 = fp16((acc + bias[col]) * qmul[(row/36)*N+col])
// alMode 0: none; 1: direct store; 3: half-head partial store to doubled buffer
// pdl 0: none; 1: wait at start; 2: wait before epilogue (qmul dep);
//     3: chunk0 = B loads, wait, A loads (A dep on predecessor)
#define KC 64

template<int MR>
__global__ __launch_bounds__(MR*4, 1) void gemm1(
    const fp16* __restrict__ A, const fp16* __restrict__ B,
    int N, int Kp, int kcTotal, int kcPerSplit,
    const float* __restrict__ bias, const float* __restrict__ qmul,
    float* __restrict__ Cf, fp16* __restrict__ C16,
    int mode, size_t splitStride,
    const float* __restrict__ a_s, const float* __restrict__ a_d,
    float* __restrict__ als, float* __restrict__ ald,
    int alMode, int alH, int alC, int pdl)
{
    constexpr int THREADS = MR * 4;
    constexpr uint32_t ABYTES = (uint32_t)MR * 128u;
    constexpr uint32_t BUFSZ = ABYTES + 32768u;
    constexpr int MW = MR / 32;

    extern __shared__ char dsm[];
    __shared__ float s_al[2][MR];
    uint32_t sb = smem_u32(dsm);
    sb = (sb + 1023u) & ~1023u;

    PDL_TRIGGER();

    const int tid = threadIdx.x;
    const int wid = tid >> 5;
    const int L   = tid & 31;
    const int m0 = blockIdx.y * MR;
    const int n0 = blockIdx.x * 256;
    const int kc0 = blockIdx.z * kcPerSplit;
    int kc1 = kc0 + kcPerSplit; if (kc1 > kcTotal) kc1 = kcTotal;
    const int ncl = kc1 - kc0;

    const int wm = (wid % MW) * 32;
    const int wn = (wid / MW) * 64;

    float acc[2][8][4];
    #pragma unroll
    for (int i = 0; i < 2; i++)
        #pragma unroll
        for (int j = 0; j < 8; j++)
            #pragma unroll
            for (int k = 0; k < 4; k++) acc[i][j][k] = 0.f;

    const int rA = ((L >> 3) & 1) * 8 + (L & 7);
    const int cA = (L >> 4) * 16;
    const int rB = (L >> 4) * 8 + (L & 7);
    const int cB = ((L >> 3) & 1) * 16;

    uint32_t offA[2], mskA[2];
    #pragma unroll
    for (int mf = 0; mf < 2; mf++) {
        int row = wm + mf * 16 + rA;
        offA[mf] = (uint32_t)(row * 128);
        mskA[mf] = (uint32_t)((row & 7) * 16);
    }
    uint32_t offB[4], mskB[4];
    #pragma unroll
    for (int nf2 = 0; nf2 < 4; nf2++) {
        int row = wn + nf2 * 16 + rB;
        offB[nf2] = (uint32_t)(row * 128);
        mskB[nf2] = (uint32_t)((row & 7) * 16);
    }

    auto load_A = [&](int c, int s) {
        const int k0 = c * KC;
        uint32_t base = sb + (uint32_t)s * BUFSZ;
        #pragma unroll
        for (int i = 0; i < (MR * 8) / THREADS; i++) {
            int u = tid + i * THREADS;
            int r = u >> 3, uc = u & 7;
            uint32_t so = SWZ128((uint32_t)(r * 128 + uc * 16));
            cpa16(base + so, A + (size_t)(m0 + r) * Kp + k0 + uc * 8);
        }
    };
    auto load_B = [&](int c, int s) {
        const int k0 = c * KC;
        uint32_t base = sb + (uint32_t)s * BUFSZ;
        #pragma unroll
        for (int i = 0; i < 2048 / THREADS; i++) {
            int u = tid + i * THREADS;
            int r = u >> 3, uc = u & 7;
            uint32_t so = SWZ128((uint32_t)(r * 128 + uc * 16));
            cpa16(base + ABYTES + so, B + (size_t)(n0 + r) * Kp + k0 + uc * 8);
        }
    };

    if (pdl == 1) PDL_WAIT();
    if (pdl == 3) {
        load_B(kc0, 0);       // weights: independent of predecessor
        PDL_WAIT();           // predecessor wrote A
        load_A(kc0, 0);
    } else {
        load_A(kc0, 0);
        load_B(kc0, 0);
    }
    CP_COMMIT();

    for (int cc = 0; cc < ncl; cc++) {
        if (cc + 1 < ncl) {
            load_A(kc0 + cc + 1, (cc + 1) & 1);
            load_B(kc0 + cc + 1, (cc + 1) & 1);
            CP_COMMIT();
            CP_WAIT1();
        } else {
            CP_WAIT0();
        }
        __syncthreads();

        uint32_t base = sb + (uint32_t)(cc & 1) * BUFSZ;
        #pragma unroll
        for (int ks = 0; ks < 4; ks++) {
            const uint32_t kb = (uint32_t)(ks * 32);
            uint32_t af[2][4];
            #pragma unroll
            for (int mf = 0; mf < 2; mf++) {
                uint32_t rel = offA[mf] + ((kb + cA) ^ mskA[mf]);
                ldmx4(af[mf][0], af[mf][1], af[mf][2], af[mf][3], base + rel);
            }
            #pragma unroll
            for (int nf2 = 0; nf2 < 4; nf2++) {
                uint32_t rel = offB[nf2] + ((kb + cB) ^ mskB[nf2]);
                uint32_t bf[4];
                ldmx4(bf[0], bf[1], bf[2], bf[3], base + ABYTES + rel);
                #pragma unroll
                for (int mf = 0; mf < 2; mf++) {
                    mma16816(acc[mf][nf2*2],   af[mf], bf[0], bf[1]);
                    mma16816(acc[mf][nf2*2+1], af[mf], bf[2], bf[3]);
                }
            }
        }
        __syncthreads();
    }

    if (pdl == 2) PDL_WAIT();   // epilogue needs qmul (combq output)

    // ---- epilogue: store C ----
    const int rEp = (L >> 2);
    const int cEp = (L & 3) * 2;
    #pragma unroll
    for (int mf = 0; mf < 2; mf++) {
        #pragma unroll
        for (int half = 0; half < 2; half++) {
            int row = m0 + wm + mf * 16 + rEp + half * 8;
            if (mode == 0) {
                float* dst = Cf + splitStride * blockIdx.z + (size_t)row * N;
                #pragma unroll
                for (int nf = 0; nf < 8; nf++) {
                    int col = n0 + wn + nf * 8 + cEp;
                    float2 v;
                    v.x = acc[mf][nf][half*2 + 0];
                    v.y = acc[mf][nf][half*2 + 1];
                    *(float2*)(dst + col) = v;
                }
            } else if (mode == 1) {
                fp16* d16 = C16 + (size_t)row * N;
                #pragma unroll
                for (int nf = 0; nf < 8; nf++) {
                    int col = n0 + wn + nf * 8 + cEp;
                    *(__half2*)(d16 + col) =
                        __floats2half2_rn(acc[mf][nf][half*2+0], acc[mf][nf][half*2+1]);
                }
            } else {
                const float* qrow = qmul + (size_t)(row / NOBJ) * N;
                fp16* d16 = C16 + (size_t)row * N;
                #pragma unroll
                for (int nf = 0; nf < 8; nf++) {
                    int col = n0 + wn + nf * 8 + cEp;
                    float o0 = (acc[mf][nf][half*2+0] + bias[col])   * qrow[col];
                    float o1 = (acc[mf][nf][half*2+1] + bias[col+1]) * qrow[col+1];
                    *(__half2*)(d16 + col) = __floats2half2_rn(o0, o1);
                }
            }
        }
    }

    // ---- fused attention logits (from exact fp32 accumulators) ----
    if (alMode) {
        if (tid < MR) { s_al[0][tid] = 0.f; s_al[1][tid] = 0.f; }
        __syncthreads();
        const int hd = n0 / alC;
        const int chBase = (n0 % alC) + wn + cEp;
        float asr[16], adr[16];
        #pragma unroll
        for (int nf = 0; nf < 8; nf++) {
            #pragma unroll
            for (int j = 0; j < 2; j++) {
                int ch = chBase + nf * 8 + j;
                asr[nf*2+j] = a_s[(size_t)hd * alC + ch];
                adr[nf*2+j] = a_d[(size_t)hd * alC + ch];
            }
        }
        #pragma unroll
        for (int mf = 0; mf < 2; mf++) {
            #pragma unroll
            for (int half = 0; half < 2; half++) {
                float ps = 0.f, pd = 0.f;
                #pragma unroll
                for (int nf = 0; nf < 8; nf++) {
                    #pragma unroll
                    for (int j = 0; j < 2; j++) {
                        float v = acc[mf][nf][half*2 + j];
                        ps = fmaf(v, asr[nf*2+j], ps);
                        pd = fmaf(v, adr[nf*2+j], pd);
                    }
                }
                ps += __shfl_xor_sync(0xffffffffu, ps, 1);
                ps += __shfl_xor_sync(0xffffffffu, ps, 2);
                pd += __shfl_xor_sync(0xffffffffu, pd, 1);
                pd += __shfl_xor_sync(0xffffffffu, pd, 2);
                if ((L & 3) == 0) {
                    int r = wm + mf * 16 + rEp + half * 8;
                    atomicAdd(&s_al[0][r], ps);
                    atomicAdd(&s_al[1][r], pd);
                }
            }
        }
        __syncthreads();
        if (tid < MR) {
            if (alMode == 1) {
                size_t oi = (size_t)(m0 + tid) * alH + hd;
                als[oi] = s_al[0][tid];
                ald[oi] = s_al[1][tid];
            } else {
                int part = (n0 % alC) >> 8;
                size_t oi = ((size_t)(m0 + tid) * alH + hd) * 2 + part;
                als[oi] = s_al[0][tid];
                ald[oi] = s_al[1][tid];
            }
        }
    }
}

// ==================== softmax helper ====================
__device__ __forceinline__ void softmax36(const float* ss, const float* sd,
                                          float (*aT)[40], int i)
{
    float di = sd[i];
    float ev[36];
    float m = -3.4e38f;
    #pragma unroll
    for (int j = 0; j < 36; j++) {
        float e = ss[j] + di;
        e = (e > 0.f) ? e : 0.2f * e;
        ev[j] = e;
        m = fmaxf(m, e);
    }
    float sum = 0.f;
    #pragma unroll
    for (int j = 0; j < 36; j++) { float x = expf(ev[j] - m); ev[j] = x; sum += x; }
    float inv = 1.0f / (sum + 1e-16f);
    #pragma unroll
    for (int j = 0; j < 36; j++) aT[j][i] = ev[j] * inv;
}

// GAT aggregation C=256 concat + relu (+fp16 residual), all-fp16 I/O
__global__ __launch_bounds__(256) void gat_agg256(
    const fp16* __restrict__ h16, const float* __restrict__ als, const float* __restrict__ ald,
    const float* __restrict__ bias, const fp16* __restrict__ resid16,
    fp16* __restrict__ out16, int H)
{
    __shared__ float sh[36][256];
    __shared__ float aT[36][40];
    __shared__ float ss[36], sd[36];

    PDL_TRIGGER();
    PDL_WAIT();

    const int bh = blockIdx.x;
    const int b = bh / H, hd = bh - b * H;
    const int tid = threadIdx.x;
    const int stride = H * 256;
    const fp16* hbase = h16 + (size_t)(b * NOBJ) * stride + hd * 256;

    for (int idx = tid; idx < 36 * 32; idx += 256) {
        int i = idx >> 5, c8 = (idx & 31) * 8;
        uint4 raw = *(const uint4*)(hbase + (size_t)i * stride + c8);
        const __half2* hp = (const __half2*)&raw;
        #pragma unroll
        for (int j = 0; j < 4; j++) {
            float2 f = __half22float2(hp[j]);
            sh[i][c8 + j*2]     = f.x;
            sh[i][c8 + j*2 + 1] = f.y;
        }
    }
    if (tid < 36) {
        ss[tid] = als[(size_t)(b * NOBJ + tid) * H + hd];
        sd[tid] = ald[(size_t)(b * NOBJ + tid) * H + hd];
    }
    __syncthreads();
    if (tid < 36) softmax36(ss, sd, aT, tid);
    __syncthreads();

    const int c = tid;
    float acc[36];
    #pragma unroll
    for (int i = 0; i < 36; i++) acc[i] = 0.f;

    #pragma unroll 4
    for (int j = 0; j < 36; j++) {
        float hv = sh[j][c];
        #pragma unroll
        for (int it = 0; it < 9; it++) {
            float4 a = *(const float4*)&aT[j][it * 4];
            acc[it*4+0] = fmaf(a.x, hv, acc[it*4+0]);
            acc[it*4+1] = fmaf(a.y, hv, acc[it*4+1]);
            acc[it*4+2] = fmaf(a.z, hv, acc[it*4+2]);
            acc[it*4+3] = fmaf(a.w, hv, acc[it*4+3]);
        }
    }

    float bv = bias[hd * 256 + c];
    #pragma unroll 4
    for (int i = 0; i < 36; i++) {
        size_t oi = (size_t)(b * NOBJ + i) * stride + hd * 256 + c;
        float o = fmaxf(acc[i] + bv, 0.f);
        if (resid16) o += __half2float(resid16[oi]);
        out16[oi] = __float2half_rn(o);
    }
}

// GAT layer 3: C=512, H=5, mean over heads + b3; logits from doubled partial buffers
__global__ __launch_bounds__(256) void gat_mean_k(
    const fp16* __restrict__ h16, const float* __restrict__ als2, const float* __restrict__ ald2,
    const float* __restrict__ bias, float* __restrict__ out)
{
    __shared__ float sh[36][256];
    __shared__ float aT[36][40];
    __shared__ float ss[36], sd[36];

    PDL_TRIGGER();
    PDL_WAIT();

    const int b = blockIdx.x;
    const int coff = blockIdx.y * 256;
    const int tid = threadIdx.x;

    float acc[36];
    #pragma unroll
    for (int i = 0; i < 36; i++) acc[i] = 0.f;

    for (int hd = 0; hd < 5; hd++) {
        __syncthreads();
        for (int idx = tid; idx < 36 * 32; idx += 256) {
            int i = idx >> 5, c8 = (idx & 31) * 8;
            uint4 raw = *(const uint4*)(h16 + (size_t)(b * NOBJ + i) * 2560 + hd * 512 + coff + c8);
            const __half2* hp = (const __half2*)&raw;
            #pragma unroll
            for (int j = 0; j < 4; j++) {
                float2 f = __half22float2(hp[j]);
                sh[i][c8 + j*2]     = f.x;
                sh[i][c8 + j*2 + 1] = f.y;
            }
        }
        if (tid < 36) {
            size_t base = ((size_t)(b * NOBJ + tid) * 5 + hd) * 2;
            ss[tid] = als2[base] + als2[base + 1];
            sd[tid] = ald2[base] + ald2[base + 1];
        }
        __syncthreads();
        if (tid < 36) softmax36(ss, sd, aT, tid);
        __syncthreads();

        const int c = tid;
        #pragma unroll 4
        for (int j = 0; j < 36; j++) {
            float hv = sh[j][c];
            #pragma unroll
            for (int it = 0; it < 9; it++) {
                float4 a = *(const float4*)&aT[j][it * 4];
                acc[it*4+0] = fmaf(a.x, hv, acc[it*4+0]);
                acc[it*4+1] = fmaf(a.y, hv, acc[it*4+1]);
                acc[it*4+2] = fmaf(a.z, hv, acc[it*4+2]);
                acc[it*4+3] = fmaf(a.w, hv, acc[it*4+3]);
            }
        }
    }

    float bv = bias[coff + tid];
    #pragma unroll 4
    for (int i = 0; i < 36; i++)
        out[(size_t)(b * NOBJ + i) * 512 + coff + tid] = acc[i] * 0.2f + bv;
}

// ==================== launch helpers ====================
static inline void pdl_cfg(cudaLaunchConfig_t& cfg, cudaLaunchAttribute* at,
                           dim3 grid, dim3 block, size_t smem)
{
    cfg = {};
    cfg.gridDim = grid; cfg.blockDim = block;
    cfg.dynamicSmemBytes = smem; cfg.stream = 0;
    at[0].id = cudaLaunchAttributeProgrammaticStreamSerialization;
    at[0].val.programmaticStreamSerializationAllowed = 1;
    cfg.attrs = at; cfg.numAttrs = 1;
}

// ==================== launch ====================
extern "C" void kernel_launch(void* const* d_in, const int* in_sizes, int n_in,
                              void* d_out, int out_size)
{
    const float* qe  = (const float*)d_in[0];
    const float* obj = (const float*)d_in[1];
    const float* Wq  = (const float*)d_in[3];
    const float* bq  = (const float*)d_in[4];
    const float* Wv  = (const float*)d_in[5];
    const float* bv  = (const float*)d_in[6];
    const float* W1  = (const float*)d_in[7];
    const float* a1s = (const float*)d_in[8];
    const float* a1d = (const float*)d_in[9];
    const float* b1  = (const float*)d_in[10];
    const float* W2  = (const float*)d_in[11];
    const float* a2s = (const float*)d_in[12];
    const float* a2d = (const float*)d_in[13];
    const float* b2  = (const float*)d_in[14];
    const float* W3  = (const float*)d_in[15];
    const float* a3s = (const float*)d_in[16];
    const float* a3d = (const float*)d_in[17];
    const float* b3  = (const float*)d_in[18];
    float* out = (float*)d_out;

    fp16 *qe16,*ob16,*WqT,*WvT,*W1T,*W2T,*W3T,*x16,*h16,*g116,*g216;
    float *q,*qpart,*als,*ald,*als2,*ald2;
    cudaGetSymbolAddress((void**)&qe16, g_qe16); cudaGetSymbolAddress((void**)&ob16, g_ob16);
    cudaGetSymbolAddress((void**)&WqT,  g_WqT);  cudaGetSymbolAddress((void**)&WvT,  g_WvT);
    cudaGetSymbolAddress((void**)&W1T,  g_W1T);  cudaGetSymbolAddress((void**)&W2T,  g_W2T);
    cudaGetSymbolAddress((void**)&W3T,  g_W3T);
    cudaGetSymbolAddress((void**)&x16,  g_x16);  cudaGetSymbolAddress((void**)&h16,  g_h16);
    cudaGetSymbolAddress((void**)&g116, g_g116); cudaGetSymbolAddress((void**)&g216, g_g216);
    cudaGetSymbolAddress((void**)&q,    g_q);    cudaGetSymbolAddress((void**)&qpart,g_qpart);
    cudaGetSymbolAddress((void**)&als,  g_als);  cudaGetSymbolAddress((void**)&ald,  g_ald);
    cudaGetSymbolAddress((void**)&als2, g_als2); cudaGetSymbolAddress((void**)&ald2, g_ald2);

    const int SMEM128 = 2 * (128 * 128 + 32768) + 1024;
    const int SMEM64  = 2 * (64 * 128 + 32768) + 1024;
    cudaFuncSetAttribute(gemm1<128>, cudaFuncAttributeMaxDynamicSharedMemorySize, SMEM128);
    cudaFuncSetAttribute(gemm1<64>,  cudaFuncAttributeMaxDynamicSharedMemorySize, SMEM64);

    // ---- batched prep: qe/obj conv + 5 weight transposes, ONE launch ----
    {
        PJobs jobs;
        int cursor = 0;
        auto addT = [&](int i, const float* W, fp16* WT, int K, int N, int Kp) {
            jobs.j[i] = { W, WT, K, N, Kp, cursor, N / 64, 1 };
            cursor += (N / 64) * (Kp / 64);
        };
        auto addC = [&](int i, const float* src, fp16* dst, int R, int C, int Cp) {
            int blocks = (R * (Cp / 16) + 255) / 256;
            jobs.j[i] = { src, dst, R, C, Cp, cursor, 0, 0 };
            cursor += blocks;
        };
        addT(0, Wq, WqT, QD,   2048, QDP);
        addT(1, Wv, WvT, 2048, 2048, 2048);
        addT(2, W1, W1T, 2048, 1024, 2048);
        addT(3, W2, W2T, 1024, 1024, 1024);
        addT(4, W3, W3T, 1024, 2560, 1024);
        addC(5, qe,  qe16, 128,   QD,   QDP);
        addC(6, obj, ob16, NNODE, 2048, 2048);
        prep_all<<<cursor, 256>>>(jobs);
    }

    cudaLaunchConfig_t cfg; cudaLaunchAttribute at[1];

    // q = qe @ Wq (split-K 8, M-tile 64): NORMAL launch (waits for prep)
    gemm1<64><<<dim3(8, 2, 8), 256, SMEM64>>>(qe16, WqT, 2048, QDP, 38, 5,
                                              (const float*)nullptr, (const float*)nullptr,
                                              qpart, (fp16*)nullptr, 0, (size_t)128 * 2048,
                                              (const float*)nullptr, (const float*)nullptr,
                                              (float*)nullptr, (float*)nullptr, 0, 1, 1, 0);

    // combq: PDL (early launch, waits for q inside)
    pdl_cfg(cfg, at, dim3((128 * 2048 + 255) / 256), dim3(256), 0);
    cudaLaunchKernelEx(&cfg, combq_k, (const float*)qpart, bq, q);

    // x = (obj @ Wv + bv) * q: PDL pdl=2 — mainloop free, wait before epilogue
    pdl_cfg(cfg, at, dim3(8, 36, 1), dim3(512), SMEM128);
    cudaLaunchKernelEx(&cfg, gemm1<128>, (const fp16*)ob16, (const fp16*)WvT,
                       2048, 2048, 32, 32, bv, (const float*)q,
                       (float*)nullptr, x16, 2, (size_t)0,
                       (const float*)nullptr, (const float*)nullptr,
                       (float*)nullptr, (float*)nullptr, 0, 1, 1, 2);

    // layer 1: PDL pdl=3 — B(W1T) first, wait, A(x16)
    pdl_cfg(cfg, at, dim3(4, 36, 1), dim3(512), SMEM128);
    cudaLaunchKernelEx(&cfg, gemm1<128>, (const fp16*)x16, (const fp16*)W1T,
                       1024, 2048, 32, 32, (const float*)nullptr, (const float*)nullptr,
                       (float*)nullptr, h16, 1, (size_t)0,
                       a1s, a1d, als, ald, 1, 4, 256, 3);
    pdl_cfg(cfg, at, dim3(BATCH * 4), dim3(256), 0);
    cudaLaunchKernelEx(&cfg, gat_agg256, (const fp16*)h16, (const float*)als, (const float*)ald,
                       b1, (const fp16*)nullptr, g116, 4);

    // layer 2: PDL pdl=3
    pdl_cfg(cfg, at, dim3(4, 36, 1), dim3(512), SMEM128);
    cudaLaunchKernelEx(&cfg, gemm1<128>, (const fp16*)g116, (const fp16*)W2T,
                       1024, 1024, 16, 16, (const float*)nullptr, (const float*)nullptr,
                       (float*)nullptr, h16, 1, (size_t)0,
                       a2s, a2d, als, ald, 1, 4, 256, 3);
    pdl_cfg(cfg, at, dim3(BATCH * 4), dim3(256), 0);
    cudaLaunchKernelEx(&cfg, gat_agg256, (const fp16*)h16, (const float*)als, (const float*)ald,
                       b2, (const fp16*)g116, g216, 4);

    // layer 3: PDL pdl=3, M-tile 64
    pdl_cfg(cfg, at, dim3(10, 72, 1), dim3(256), SMEM64);
    cudaLaunchKernelEx(&cfg, gemm1<64>, (const fp16*)g216, (const fp16*)W3T,
                       2560, 1024, 16, 16, (const float*)nullptr, (const float*)nullptr,
                       (float*)nullptr, h16, 1, (size_t)0,
                       a3s, a3d, als2, ald2, 3, 5, 512, 3);
    pdl_cfg(cfg, at, dim3(BATCH, 2), dim3(256), 0);
    cudaLaunchKernelEx(&cfg, gat_mean_k, (const fp16*)h16, (const float*)als2, (const float*)ald2,
                       b3, out);

    (void)in_sizes; (void)n_in; (void)out_size;
}

// round 13
// speedup vs baseline: 1.7148x; 1.0321x over previous
#include <cuda_runtime.h>
#include <cuda_fp16.h>
#include <math.h>
#include <stdint.h>

// Problem constants
#define BATCH 128
#define NOBJ  36
#define NNODE (BATCH*NOBJ)   // 4608
#define QD    2400
#define QDP   2432

typedef __half fp16;

#define SWZ128(o) ((o) ^ (((o) >> 3) & 0x70))

#define PDL_TRIGGER() asm volatile("griddepcontrol.launch_dependents;" ::: "memory")
#define PDL_WAIT()    asm volatile("griddepcontrol.wait;" ::: "memory")

__device__ __forceinline__ uint32_t smem_u32(const void* p) {
    uint32_t a;
    asm("{ .reg .u64 t; cvta.to.shared.u64 t, %1; cvt.u32.u64 %0, t; }" : "=r"(a) : "l"(p));
    return a;
}
__device__ __forceinline__ void cpa16(uint32_t s, const void* g) {
    asm volatile("cp.async.cg.shared.global [%0], [%1], 16;" :: "r"(s), "l"(g));
}
#define CP_COMMIT() asm volatile("cp.async.commit_group;" ::: "memory")
#define CP_WAIT1()  asm volatile("cp.async.wait_group 1;" ::: "memory")
#define CP_WAIT0()  asm volatile("cp.async.wait_group 0;" ::: "memory")

__device__ __forceinline__ void ldmx4(uint32_t& r0, uint32_t& r1, uint32_t& r2, uint32_t& r3, uint32_t addr) {
    asm volatile("ldmatrix.sync.aligned.m8n8.x4.shared.b16 {%0,%1,%2,%3}, [%4];"
                 : "=r"(r0), "=r"(r1), "=r"(r2), "=r"(r3) : "r"(addr));
}
__device__ __forceinline__ void mma16816(float* c, const uint32_t* a, uint32_t b0, uint32_t b1) {
    asm volatile(
        "mma.sync.aligned.m16n8k16.row.col.f32.f16.f16.f32 "
        "{%0,%1,%2,%3}, {%4,%5,%6,%7}, {%8,%9}, {%0,%1,%2,%3};"
        : "+f"(c[0]), "+f"(c[1]), "+f"(c[2]), "+f"(c[3])
        : "r"(a[0]), "r"(a[1]), "r"(a[2]), "r"(a[3]), "r"(b0), "r"(b1));
}

// ==================== scratch (no allocations allowed) ====================
__device__ __align__(128) fp16 g_qe16[128 * QDP];
__device__ __align__(128) fp16 g_ob16[NNODE * 2048];
__device__ __align__(128) fp16 g_WqT [2048 * QDP];
__device__ __align__(128) fp16 g_WvT [2048 * 2048];
__device__ __align__(128) fp16 g_W1T [1024 * 2048];
__device__ __align__(128) fp16 g_W2T [1024 * 1024];
__device__ __align__(128) fp16 g_W3T [2560 * 1024];
__device__ __align__(128) fp16 g_x16 [NNODE * 2048];
__device__ __align__(128) fp16 g_h16 [NNODE * 2560];
__device__ __align__(128) fp16 g_g116[NNODE * 1024];
__device__ __align__(128) fp16 g_g216[NNODE * 1024];

__device__ float g_q    [128 * 2048];
__device__ float g_qpart[8 * 128 * 2048];
__device__ float g_als  [NNODE * 5];
__device__ float g_ald  [NNODE * 5];
__device__ float g_als2 [NNODE * 5 * 2];
__device__ float g_ald2 [NNODE * 5 * 2];

// ==================== batched prep ====================
struct PJob { const float* src; fp16* dst; int K, N, Kp, start, tX, type; };
struct PJobs { PJob j[7]; };

__global__ __launch_bounds__(256) void prep_all(PJobs jobs)
{
    __shared__ float t[64][65];
    PDL_TRIGGER();
    int b = blockIdx.x;
    int ji = 0;
    #pragma unroll
    for (int i = 1; i < 7; i++) if (b >= jobs.j[i].start) ji = i;
    const PJob jb = jobs.j[ji];
    const int tt = b - jb.start;
    const int tid = threadIdx.x;

    if (jb.type == 0) {
        int g = tt * 256 + tid;
        int cq = jb.Kp >> 4;
        if (g >= jb.K * cq) return;
        int r = g / cq;
        int c16 = (g - r * cq) * 16;
        const float* src = jb.src + (size_t)r * jb.N + c16;
        fp16* dst = jb.dst + (size_t)r * jb.Kp + c16;
        __half2 o[8];
        #pragma unroll
        for (int j = 0; j < 4; j++) {
            float4 v = make_float4(0.f, 0.f, 0.f, 0.f);
            if (c16 + j * 4 < jb.N) v = *(const float4*)(src + j * 4);
            o[j*2+0] = __floats2half2_rn(v.x, v.y);
            o[j*2+1] = __floats2half2_rn(v.z, v.w);
        }
        *(uint4*)(dst)     = *(uint4*)&o[0];
        *(uint4*)(dst + 8) = *(uint4*)&o[4];
    } else {
        const int n0 = (tt % jb.tX) * 64;
        const int k0 = (tt / jb.tX) * 64;
        {
            int tx = tid & 15, ty = tid >> 4;
            #pragma unroll
            for (int i = 0; i < 4; i++) {
                int k = k0 + ty + i * 16;
                float4 v = make_float4(0.f, 0.f, 0.f, 0.f);
                if (k < jb.K) v = *(const float4*)(jb.src + (size_t)k * jb.N + n0 + tx * 4);
                t[ty + i * 16][tx*4+0] = v.x;
                t[ty + i * 16][tx*4+1] = v.y;
                t[ty + i * 16][tx*4+2] = v.z;
                t[ty + i * 16][tx*4+3] = v.w;
            }
        }
        __syncthreads();
        {
            int nr = tid >> 2;
            int kq = (tid & 3) * 16;
            __half2 o[8];
            #pragma unroll
            for (int j = 0; j < 8; j++)
                o[j] = __floats2half2_rn(t[kq + j*2][nr], t[kq + j*2 + 1][nr]);
            fp16* dst = jb.dst + (size_t)(n0 + nr) * jb.Kp + k0 + kq;
            *(uint4*)(dst)     = *(uint4*)&o[0];
            *(uint4*)(dst + 8) = *(uint4*)&o[4];
        }
    }
}

__global__ void combq_k(const float* __restrict__ parts, const float* __restrict__ bq, float* __restrict__ q)
{
    PDL_TRIGGER();
    PDL_WAIT();
    int idx = blockIdx.x * blockDim.x + threadIdx.x;
    if (idx >= 128 * 2048) return;
    const size_t S = (size_t)128 * 2048;
    int c = idx & 2047;
    float s = bq[c];
    #pragma unroll
    for (int p = 0; p < 8; p++) s += parts[idx + p * S];
    q[idx] = s;
}

// ==================== fp16 GEMM, warp tile 64x64, reg-pipelined frags ====================
// MR=128: 8 warps (256 th), warp grid 2x4; MR=64: 4 warps (128 th), warp grid 1x4
// N-tile 256, KC=64
#define KC 64

template<int MR>
__global__ __launch_bounds__(MR*2, 1) void gemm1(
    const fp16* __restrict__ A, const fp16* __restrict__ B,
    int N, int Kp, int kcTotal, int kcPerSplit,
    const float* __restrict__ bias, const float* __restrict__ qmul,
    float* __restrict__ Cf, fp16* __restrict__ C16,
    int mode, size_t splitStride,
    const float* __restrict__ a_s, const float* __restrict__ a_d,
    float* __restrict__ als, float* __restrict__ ald,
    int alMode, int alH, int alC, int pdl)
{
    constexpr int THREADS = MR * 2;
    constexpr uint32_t ABYTES = (uint32_t)MR * 128u;
    constexpr uint32_t BUFSZ = ABYTES + 32768u;
    constexpr int MW = MR / 64;            // warp-rows

    extern __shared__ char dsm[];
    __shared__ float s_al[2][MR];
    uint32_t sb = smem_u32(dsm);
    sb = (sb + 1023u) & ~1023u;

    PDL_TRIGGER();

    const int tid = threadIdx.x;
    const int wid = tid >> 5;
    const int L   = tid & 31;
    const int m0 = blockIdx.y * MR;
    const int n0 = blockIdx.x * 256;
    const int kc0 = blockIdx.z * kcPerSplit;
    int kc1 = kc0 + kcPerSplit; if (kc1 > kcTotal) kc1 = kcTotal;
    const int ncl = kc1 - kc0;

    const int wm = (wid % MW) * 64;
    const int wn = (wid / MW) * 64;

    float acc[4][8][4];
    #pragma unroll
    for (int i = 0; i < 4; i++)
        #pragma unroll
        for (int j = 0; j < 8; j++)
            #pragma unroll
            for (int k = 0; k < 4; k++) acc[i][j][k] = 0.f;

    const int rA = ((L >> 3) & 1) * 8 + (L & 7);
    const int cA = (L >> 4) * 16;
    const int rB = (L >> 4) * 8 + (L & 7);
    const int cB = ((L >> 3) & 1) * 16;

    uint32_t offA[4], mskA[4];
    #pragma unroll
    for (int mf = 0; mf < 4; mf++) {
        int row = wm + mf * 16 + rA;
        offA[mf] = (uint32_t)(row * 128);
        mskA[mf] = (uint32_t)((row & 7) * 16);
    }
    uint32_t offB[4], mskB[4];
    #pragma unroll
    for (int nf2 = 0; nf2 < 4; nf2++) {
        int row = wn + nf2 * 16 + rB;
        offB[nf2] = (uint32_t)(row * 128);
        mskB[nf2] = (uint32_t)((row & 7) * 16);
    }

    auto load_A = [&](int c, int s) {
        const int k0 = c * KC;
        uint32_t base = sb + (uint32_t)s * BUFSZ;
        #pragma unroll
        for (int i = 0; i < (MR * 8) / THREADS; i++) {
            int u = tid + i * THREADS;
            int r = u >> 3, uc = u & 7;
            uint32_t so = SWZ128((uint32_t)(r * 128 + uc * 16));
            cpa16(base + so, A + (size_t)(m0 + r) * Kp + k0 + uc * 8);
        }
    };
    auto load_B = [&](int c, int s) {
        const int k0 = c * KC;
        uint32_t base = sb + (uint32_t)s * BUFSZ;
        #pragma unroll
        for (int i = 0; i < 2048 / THREADS; i++) {
            int u = tid + i * THREADS;
            int r = u >> 3, uc = u & 7;
            uint32_t so = SWZ128((uint32_t)(r * 128 + uc * 16));
            cpa16(base + ABYTES + so, B + (size_t)(n0 + r) * Kp + k0 + uc * 8);
        }
    };

    if (pdl == 1) PDL_WAIT();
    if (pdl == 3) {
        load_B(kc0, 0);
        PDL_WAIT();
        load_A(kc0, 0);
    } else {
        load_A(kc0, 0);
        load_B(kc0, 0);
    }
    CP_COMMIT();

    // register-double-buffered fragments
    uint32_t afb[2][4][4], bfb[2][4][4];

    auto ldfrags = [&](uint32_t base, int ks, int buf) {
        const uint32_t kb = (uint32_t)(ks * 32);
        #pragma unroll
        for (int mf = 0; mf < 4; mf++) {
            uint32_t rel = offA[mf] + ((kb + cA) ^ mskA[mf]);
            ldmx4(afb[buf][mf][0], afb[buf][mf][1], afb[buf][mf][2], afb[buf][mf][3], base + rel);
        }
        #pragma unroll
        for (int nf2 = 0; nf2 < 4; nf2++) {
            uint32_t rel = offB[nf2] + ((kb + cB) ^ mskB[nf2]);
            ldmx4(bfb[buf][nf2][0], bfb[buf][nf2][1], bfb[buf][nf2][2], bfb[buf][nf2][3],
                  base + ABYTES + rel);
        }
    };
    auto do_mma = [&](int buf) {
        #pragma unroll
        for (int nf2 = 0; nf2 < 4; nf2++)
            #pragma unroll
            for (int mf = 0; mf < 4; mf++) {
                mma16816(acc[mf][nf2*2],   afb[buf][mf], bfb[buf][nf2][0], bfb[buf][nf2][1]);
                mma16816(acc[mf][nf2*2+1], afb[buf][mf], bfb[buf][nf2][2], bfb[buf][nf2][3]);
            }
    };

    for (int cc = 0; cc < ncl; cc++) {
        if (cc + 1 < ncl) {
            load_A(kc0 + cc + 1, (cc + 1) & 1);
            load_B(kc0 + cc + 1, (cc + 1) & 1);
            CP_COMMIT();
            CP_WAIT1();
        } else {
            CP_WAIT0();
        }
        __syncthreads();

        uint32_t base = sb + (uint32_t)(cc & 1) * BUFSZ;
        ldfrags(base, 0, 0);
        #pragma unroll
        for (int ks = 0; ks < 4; ks++) {
            if (ks < 3) ldfrags(base, ks + 1, (ks + 1) & 1);
            do_mma(ks & 1);
        }
        __syncthreads();
    }

    if (pdl == 2) PDL_WAIT();

    // ---- epilogue: store C ----
    const int rEp = (L >> 2);
    const int cEp = (L & 3) * 2;
    #pragma unroll
    for (int mf = 0; mf < 4; mf++) {
        #pragma unroll
        for (int half = 0; half < 2; half++) {
            int row = m0 + wm + mf * 16 + rEp + half * 8;
            if (mode == 0) {
                float* dst = Cf + splitStride * blockIdx.z + (size_t)row * N;
                #pragma unroll
                for (int nf = 0; nf < 8; nf++) {
                    int col = n0 + wn + nf * 8 + cEp;
                    float2 v;
                    v.x = acc[mf][nf][half*2 + 0];
                    v.y = acc[mf][nf][half*2 + 1];
                    *(float2*)(dst + col) = v;
                }
            } else if (mode == 1) {
                fp16* d16 = C16 + (size_t)row * N;
                #pragma unroll
                for (int nf = 0; nf < 8; nf++) {
                    int col = n0 + wn + nf * 8 + cEp;
                    *(__half2*)(d16 + col) =
                        __floats2half2_rn(acc[mf][nf][half*2+0], acc[mf][nf][half*2+1]);
                }
            } else {
                const float* qrow = qmul + (size_t)(row / NOBJ) * N;
                fp16* d16 = C16 + (size_t)row * N;
                #pragma unroll
                for (int nf = 0; nf < 8; nf++) {
                    int col = n0 + wn + nf * 8 + cEp;
                    float o0 = (acc[mf][nf][half*2+0] + bias[col])   * qrow[col];
                    float o1 = (acc[mf][nf][half*2+1] + bias[col+1]) * qrow[col+1];
                    *(__half2*)(d16 + col) = __floats2half2_rn(o0, o1);
                }
            }
        }
    }

    // ---- fused attention logits ----
    if (alMode) {
        if (tid < MR) { s_al[0][tid] = 0.f; s_al[1][tid] = 0.f; }
        __syncthreads();
        const int hd = n0 / alC;
        const int chBase = (n0 % alC) + wn + cEp;
        float asr[16], adr[16];
        #pragma unroll
        for (int nf = 0; nf < 8; nf++) {
            #pragma unroll
            for (int j = 0; j < 2; j++) {
                int ch = chBase + nf * 8 + j;
                asr[nf*2+j] = a_s[(size_t)hd * alC + ch];
                adr[nf*2+j] = a_d[(size_t)hd * alC + ch];
            }
        }
        #pragma unroll
        for (int mf = 0; mf < 4; mf++) {
            #pragma unroll
            for (int half = 0; half < 2; half++) {
                float ps = 0.f, pd = 0.f;
                #pragma unroll
                for (int nf = 0; nf < 8; nf++) {
                    #pragma unroll
                    for (int j = 0; j < 2; j++) {
                        float v = acc[mf][nf][half*2 + j];
                        ps = fmaf(v, asr[nf*2+j], ps);
                        pd = fmaf(v, adr[nf*2+j], pd);
                    }
                }
                ps += __shfl_xor_sync(0xffffffffu, ps, 1);
                ps += __shfl_xor_sync(0xffffffffu, ps, 2);
                pd += __shfl_xor_sync(0xffffffffu, pd, 1);
                pd += __shfl_xor_sync(0xffffffffu, pd, 2);
                if ((L & 3) == 0) {
                    int r = wm + mf * 16 + rEp + half * 8;
                    atomicAdd(&s_al[0][r], ps);
                    atomicAdd(&s_al[1][r], pd);
                }
            }
        }
        __syncthreads();
        if (tid < MR) {
            if (alMode == 1) {
                size_t oi = (size_t)(m0 + tid) * alH + hd;
                als[oi] = s_al[0][tid];
                ald[oi] = s_al[1][tid];
            } else {
                int part = (n0 % alC) >> 8;
                size_t oi = ((size_t)(m0 + tid) * alH + hd) * 2 + part;
                als[oi] = s_al[0][tid];
                ald[oi] = s_al[1][tid];
            }
        }
    }
}

// ==================== softmax helper ====================
__device__ __forceinline__ void softmax36(const float* ss, const float* sd,
                                          float (*aT)[40], int i)
{
    float di = sd[i];
    float ev[36];
    float m = -3.4e38f;
    #pragma unroll
    for (int j = 0; j < 36; j++) {
        float e = ss[j] + di;
        e = (e > 0.f) ? e : 0.2f * e;
        ev[j] = e;
        m = fmaxf(m, e);
    }
    float sum = 0.f;
    #pragma unroll
    for (int j = 0; j < 36; j++) { float x = expf(ev[j] - m); ev[j] = x; sum += x; }
    float inv = 1.0f / (sum + 1e-16f);
    #pragma unroll
    for (int j = 0; j < 36; j++) aT[j][i] = ev[j] * inv;
}

__global__ __launch_bounds__(256) void gat_agg256(
    const fp16* __restrict__ h16, const float* __restrict__ als, const float* __restrict__ ald,
    const float* __restrict__ bias, const fp16* __restrict__ resid16,
    fp16* __restrict__ out16, int H)
{
    __shared__ float sh[36][256];
    __shared__ float aT[36][40];
    __shared__ float ss[36], sd[36];

    PDL_TRIGGER();
    PDL_WAIT();

    const int bh = blockIdx.x;
    const int b = bh / H, hd = bh - b * H;
    const int tid = threadIdx.x;
    const int stride = H * 256;
    const fp16* hbase = h16 + (size_t)(b * NOBJ) * stride + hd * 256;

    for (int idx = tid; idx < 36 * 32; idx += 256) {
        int i = idx >> 5, c8 = (idx & 31) * 8;
        uint4 raw = *(const uint4*)(hbase + (size_t)i * stride + c8);
        const __half2* hp = (const __half2*)&raw;
        #pragma unroll
        for (int j = 0; j < 4; j++) {
            float2 f = __half22float2(hp[j]);
            sh[i][c8 + j*2]     = f.x;
            sh[i][c8 + j*2 + 1] = f.y;
        }
    }
    if (tid < 36) {
        ss[tid] = als[(size_t)(b * NOBJ + tid) * H + hd];
        sd[tid] = ald[(size_t)(b * NOBJ + tid) * H + hd];
    }
    __syncthreads();
    if (tid < 36) softmax36(ss, sd, aT, tid);
    __syncthreads();

    const int c = tid;
    float acc[36];
    #pragma unroll
    for (int i = 0; i < 36; i++) acc[i] = 0.f;

    #pragma unroll 4
    for (int j = 0; j < 36; j++) {
        float hv = sh[j][c];
        #pragma unroll
        for (int it = 0; it < 9; it++) {
            float4 a = *(const float4*)&aT[j][it * 4];
            acc[it*4+0] = fmaf(a.x, hv, acc[it*4+0]);
            acc[it*4+1] = fmaf(a.y, hv, acc[it*4+1]);
            acc[it*4+2] = fmaf(a.z, hv, acc[it*4+2]);
            acc[it*4+3] = fmaf(a.w, hv, acc[it*4+3]);
        }
    }

    float bv = bias[hd * 256 + c];
    #pragma unroll 4
    for (int i = 0; i < 36; i++) {
        size_t oi = (size_t)(b * NOBJ + i) * stride + hd * 256 + c;
        float o = fmaxf(acc[i] + bv, 0.f);
        if (resid16) o += __half2float(resid16[oi]);
        out16[oi] = __float2half_rn(o);
    }
}

__global__ __launch_bounds__(256) void gat_mean_k(
    const fp16* __restrict__ h16, const float* __restrict__ als2, const float* __restrict__ ald2,
    const float* __restrict__ bias, float* __restrict__ out)
{
    __shared__ float sh[36][256];
    __shared__ float aT[36][40];
    __shared__ float ss[36], sd[36];

    PDL_TRIGGER();
    PDL_WAIT();

    const int b = blockIdx.x;
    const int coff = blockIdx.y * 256;
    const int tid = threadIdx.x;

    float acc[36];
    #pragma unroll
    for (int i = 0; i < 36; i++) acc[i] = 0.f;

    for (int hd = 0; hd < 5; hd++) {
        __syncthreads();
        for (int idx = tid; idx < 36 * 32; idx += 256) {
            int i = idx >> 5, c8 = (idx & 31) * 8;
            uint4 raw = *(const uint4*)(h16 + (size_t)(b * NOBJ + i) * 2560 + hd * 512 + coff + c8);
            const __half2* hp = (const __half2*)&raw;
            #pragma unroll
            for (int j = 0; j < 4; j++) {
                float2 f = __half22float2(hp[j]);
                sh[i][c8 + j*2]     = f.x;
                sh[i][c8 + j*2 + 1] = f.y;
            }
        }
        if (tid < 36) {
            size_t base = ((size_t)(b * NOBJ + tid) * 5 + hd) * 2;
            ss[tid] = als2[base] + als2[base + 1];
            sd[tid] = ald2[base] + ald2[base + 1];
        }
        __syncthreads();
        if (tid < 36) softmax36(ss, sd, aT, tid);
        __syncthreads();

        const int c = tid;
        #pragma unroll 4
        for (int j = 0; j < 36; j++) {
            float hv = sh[j][c];
            #pragma unroll
            for (int it = 0; it < 9; it++) {
                float4 a = *(const float4*)&aT[j][it * 4];
                acc[it*4+0] = fmaf(a.x, hv, acc[it*4+0]);
                acc[it*4+1] = fmaf(a.y, hv, acc[it*4+1]);
                acc[it*4+2] = fmaf(a.z, hv, acc[it*4+2]);
                acc[it*4+3] = fmaf(a.w, hv, acc[it*4+3]);
            }
        }
    }

    float bv = bias[coff + tid];
    #pragma unroll 4
    for (int i = 0; i < 36; i++)
        out[(size_t)(b * NOBJ + i) * 512 + coff + tid] = acc[i] * 0.2f + bv;
}

// ==================== launch helpers ====================
static inline void pdl_cfg(cudaLaunchConfig_t& cfg, cudaLaunchAttribute* at,
                           dim3 grid, dim3 block, size_t smem)
{
    cfg = {};
    cfg.gridDim = grid; cfg.blockDim = block;
    cfg.dynamicSmemBytes = smem; cfg.stream = 0;
    at[0].id = cudaLaunchAttributeProgrammaticStreamSerialization;
    at[0].val.programmaticStreamSerializationAllowed = 1;
    cfg.attrs = at; cfg.numAttrs = 1;
}

// ==================== launch ====================
extern "C" void kernel_launch(void* const* d_in, const int* in_sizes, int n_in,
                              void* d_out, int out_size)
{
    const float* qe  = (const float*)d_in[0];
    const float* obj = (const float*)d_in[1];
    const float* Wq  = (const float*)d_in[3];
    const float* bq  = (const float*)d_in[4];
    const float* Wv  = (const float*)d_in[5];
    const float* bv  = (const float*)d_in[6];
    const float* W1  = (const float*)d_in[7];
    const float* a1s = (const float*)d_in[8];
    const float* a1d = (const float*)d_in[9];
    const float* b1  = (const float*)d_in[10];
    const float* W2  = (const float*)d_in[11];
    const float* a2s = (const float*)d_in[12];
    const float* a2d = (const float*)d_in[13];
    const float* b2  = (const float*)d_in[14];
    const float* W3  = (const float*)d_in[15];
    const float* a3s = (const float*)d_in[16];
    const float* a3d = (const float*)d_in[17];
    const float* b3  = (const float*)d_in[18];
    float* out = (float*)d_out;

    fp16 *qe16,*ob16,*WqT,*WvT,*W1T,*W2T,*W3T,*x16,*h16,*g116,*g216;
    float *q,*qpart,*als,*ald,*als2,*ald2;
    cudaGetSymbolAddress((void**)&qe16, g_qe16); cudaGetSymbolAddress((void**)&ob16, g_ob16);
    cudaGetSymbolAddress((void**)&WqT,  g_WqT);  cudaGetSymbolAddress((void**)&WvT,  g_WvT);
    cudaGetSymbolAddress((void**)&W1T,  g_W1T);  cudaGetSymbolAddress((void**)&W2T,  g_W2T);
    cudaGetSymbolAddress((void**)&W3T,  g_W3T);
    cudaGetSymbolAddress((void**)&x16,  g_x16);  cudaGetSymbolAddress((void**)&h16,  g_h16);
    cudaGetSymbolAddress((void**)&g116, g_g116); cudaGetSymbolAddress((void**)&g216, g_g216);
    cudaGetSymbolAddress((void**)&q,    g_q);    cudaGetSymbolAddress((void**)&qpart,g_qpart);
    cudaGetSymbolAddress((void**)&als,  g_als);  cudaGetSymbolAddress((void**)&ald,  g_ald);
    cudaGetSymbolAddress((void**)&als2, g_als2); cudaGetSymbolAddress((void**)&ald2, g_ald2);

    const int SMEM128 = 2 * (128 * 128 + 32768) + 1024;   // 99328
    const int SMEM64  = 2 * (64 * 128 + 32768) + 1024;    // 82944
    cudaFuncSetAttribute(gemm1<128>, cudaFuncAttributeMaxDynamicSharedMemorySize, SMEM128);
    cudaFuncSetAttribute(gemm1<64>,  cudaFuncAttributeMaxDynamicSharedMemorySize, SMEM64);

    // ---- batched prep (one launch) ----
    {
        PJobs jobs;
        int cursor = 0;
        auto addT = [&](int i, const float* W, fp16* WT, int K, int N, int Kp) {
            jobs.j[i] = { W, WT, K, N, Kp, cursor, N / 64, 1 };
            cursor += (N / 64) * (Kp / 64);
        };
        auto addC = [&](int i, const float* src, fp16* dst, int R, int C, int Cp) {
            int blocks = (R * (Cp / 16) + 255) / 256;
            jobs.j[i] = { src, dst, R, C, Cp, cursor, 0, 0 };
            cursor += blocks;
        };
        addT(0, Wq, WqT, QD,   2048, QDP);
        addT(1, Wv, WvT, 2048, 2048, 2048);
        addT(2, W1, W1T, 2048, 1024, 2048);
        addT(3, W2, W2T, 1024, 1024, 1024);
        addT(4, W3, W3T, 1024, 2560, 1024);
        addC(5, qe,  qe16, 128,   QD,   QDP);
        addC(6, obj, ob16, NNODE, 2048, 2048);
        prep_all<<<cursor, 256>>>(jobs);
    }

    cudaLaunchConfig_t cfg; cudaLaunchAttribute at[1];

    // q GEMM (MR=64, 128 threads), split-K 8
    gemm1<64><<<dim3(8, 2, 8), 128, SMEM64>>>(qe16, WqT, 2048, QDP, 38, 5,
                                              (const float*)nullptr, (const float*)nullptr,
                                              qpart, (fp16*)nullptr, 0, (size_t)128 * 2048,
                                              (const float*)nullptr, (const float*)nullptr,
                                              (float*)nullptr, (float*)nullptr, 0, 1, 1, 0);

    pdl_cfg(cfg, at, dim3((128 * 2048 + 255) / 256), dim3(256), 0);
    cudaLaunchKernelEx(&cfg, combq_k, (const float*)qpart, bq, q);

    // x GEMM: pdl=2 (wait before epilogue for q)
    pdl_cfg(cfg, at, dim3(8, 36, 1), dim3(256), SMEM128);
    cudaLaunchKernelEx(&cfg, gemm1<128>, (const fp16*)ob16, (const fp16*)WvT,
                       2048, 2048, 32, 32, bv, (const float*)q,
                       (float*)nullptr, x16, 2, (size_t)0,
                       (const float*)nullptr, (const float*)nullptr,
                       (float*)nullptr, (float*)nullptr, 0, 1, 1, 2);

    // layer 1: pdl=3
    pdl_cfg(cfg, at, dim3(4, 36, 1), dim3(256), SMEM128);
    cudaLaunchKernelEx(&cfg, gemm1<128>, (const fp16*)x16, (const fp16*)W1T,
                       1024, 2048, 32, 32, (const float*)nullptr, (const float*)nullptr,
                       (float*)nullptr, h16, 1, (size_t)0,
                       a1s, a1d, als, ald, 1, 4, 256, 3);
    pdl_cfg(cfg, at, dim3(BATCH * 4), dim3(256), 0);
    cudaLaunchKernelEx(&cfg, gat_agg256, (const fp16*)h16, (const float*)als, (const float*)ald,
                       b1, (const fp16*)nullptr, g116, 4);

    // layer 2: pdl=3
    pdl_cfg(cfg, at, dim3(4, 36, 1), dim3(256), SMEM128);
    cudaLaunchKernelEx(&cfg, gemm1<128>, (const fp16*)g116, (const fp16*)W2T,
                       1024, 1024, 16, 16, (const float*)nullptr, (const float*)nullptr,
                       (float*)nullptr, h16, 1, (size_t)0,
                       a2s, a2d, als, ald, 1, 4, 256, 3);
    pdl_cfg(cfg, at, dim3(BATCH * 4), dim3(256), 0);
    cudaLaunchKernelEx(&cfg, gat_agg256, (const fp16*)h16, (const float*)als, (const float*)ald,
                       b2, (const fp16*)g116, g216, 4);

    // layer 3: pdl=3, MR=64 (128 threads)
    pdl_cfg(cfg, at, dim3(10, 72, 1), dim3(128), SMEM64);
    cudaLaunchKernelEx(&cfg, gemm1<64>, (const fp16*)g216, (const fp16*)W3T,
                       2560, 1024, 16, 16, (const float*)nullptr, (const float*)nullptr,
                       (float*)nullptr, h16, 1, (size_t)0,
                       a3s, a3d, als2, ald2, 3, 5, 512, 3);
    pdl_cfg(cfg, at, dim3(BATCH, 2), dim3(256), 0);
    cudaLaunchKernelEx(&cfg, gat_mean_k, (const fp16*)h16, (const float*)als2, (const float*)ald2,
                       b3, out);

    (void)in_sizes; (void)n_in; (void)out_size;
}